// round 1
// baseline (speedup 1.0000x reference)
#include <cuda_runtime.h>
#include <math.h>

#define CB 2
#define CS 2048
#define CD 1024
#define CH 16
#define CDK 64
#define CM (CB*CS)   // 4096

// Scratch (allocation-free rule: __device__ globals)
__device__ float g_q[CB*CH*CS*CDK];
__device__ float g_k[CB*CH*CS*CDK];
__device__ float g_v[CB*CH*CS*CDK];
__device__ float g_attn[CB*CS*CD];
__device__ float g_trig[CS*32*2];

// ---------------------------------------------------------------------------
// GEMM: C[M=4096, N=1024] = A[4096,1024] @ W[1024,1024] + bias
// LAYOUT 0: plain row-major output. LAYOUT 1: scatter to [B,H,S,DK].
// 128x128 tile, BK=16, 256 threads, 8x8 per thread.
// ---------------------------------------------------------------------------
template<int LAYOUT>
__global__ __launch_bounds__(256, 2)
void gemm128(const float* __restrict__ A, const float* __restrict__ W,
             const float* __restrict__ bias, float* __restrict__ C)
{
    __shared__ float As[16][132];   // transposed: As[k][m]
    __shared__ float Bs[16][132];   // Bs[k][n]
    const int tid = threadIdx.x;
    const int tx = tid & 15, ty = tid >> 4;
    const int m0 = blockIdx.y << 7;
    const int n0 = blockIdx.x << 7;

    float acc[8][8];
    #pragma unroll
    for (int i = 0; i < 8; i++)
        #pragma unroll
        for (int j = 0; j < 8; j++) acc[i][j] = 0.f;

    for (int k0 = 0; k0 < CD; k0 += 16) {
        #pragma unroll
        for (int t = 0; t < 2; t++) {
            int f = tid + (t << 8);            // 0..511
            int row = f >> 2;                  // 0..127
            int kq  = (f & 3) << 2;            // 0,4,8,12
            float4 v = *(const float4*)(A + (size_t)(m0 + row) * CD + k0 + kq);
            As[kq+0][row] = v.x; As[kq+1][row] = v.y;
            As[kq+2][row] = v.z; As[kq+3][row] = v.w;
        }
        #pragma unroll
        for (int t = 0; t < 2; t++) {
            int f = tid + (t << 8);
            int row = f >> 5;                  // 0..15
            int nq  = (f & 31) << 2;           // 0..124
            *(float4*)(&Bs[row][nq]) = *(const float4*)(W + (size_t)(k0 + row) * CD + n0 + nq);
        }
        __syncthreads();
        #pragma unroll
        for (int kk = 0; kk < 16; kk++) {
            float a[8], b[8];
            *(float4*)(a)   = *(float4*)&As[kk][ty*8];
            *(float4*)(a+4) = *(float4*)&As[kk][ty*8+4];
            *(float4*)(b)   = *(float4*)&Bs[kk][tx*8];
            *(float4*)(b+4) = *(float4*)&Bs[kk][tx*8+4];
            #pragma unroll
            for (int i = 0; i < 8; i++)
                #pragma unroll
                for (int j = 0; j < 8; j++)
                    acc[i][j] = fmaf(a[i], b[j], acc[i][j]);
        }
        __syncthreads();
    }

    #pragma unroll
    for (int i = 0; i < 8; i++) {
        int m = m0 + ty*8 + i;
        #pragma unroll
        for (int jj = 0; jj < 2; jj++) {
            int n = n0 + tx*8 + jj*4;
            float4 bv = *(const float4*)(bias + n);
            float4 r;
            r.x = acc[i][jj*4+0] + bv.x;
            r.y = acc[i][jj*4+1] + bv.y;
            r.z = acc[i][jj*4+2] + bv.z;
            r.w = acc[i][jj*4+3] + bv.w;
            size_t idx;
            if (LAYOUT == 0) {
                idx = (size_t)m * CD + n;
            } else {
                int b_ = m >> 11, s_ = m & (CS - 1);
                int h_ = n >> 6,  dk = n & 63;
                idx = ((size_t)((b_*CH + h_)*CS + s_)) * CDK + dk;
            }
            *(float4*)(C + idx) = r;
        }
    }
}

// ---------------------------------------------------------------------------
// RoPE trig table: (s, i) -> cos/sin(s * 10000^(-i/32)), double-precision gen
// ---------------------------------------------------------------------------
__global__ void trig_kernel()
{
    int t = blockIdx.x * 256 + threadIdx.x;  // 0..65535
    int s = t >> 5, i = t & 31;
    double theta = exp((double)i * (-log(10000.0) / 32.0));
    double a = (double)s * theta;
    g_trig[t*2]   = (float)cos(a);
    g_trig[t*2+1] = (float)sin(a);
}

// RoPE in-place on Q and K in [B,H,S,DK] layout. One warp-lane per rotation pair.
__global__ void rope_kernel(float* __restrict__ q, float* __restrict__ k)
{
    int gid  = blockIdx.x * 256 + threadIdx.x;
    int lane = gid & 31;
    int row  = gid >> 5;               // 0 .. B*H*S-1
    int s    = row & (CS - 1);
    float c  = g_trig[(s*32 + lane)*2];
    float sn = g_trig[(s*32 + lane)*2 + 1];

    float* qr = q + (size_t)row * CDK;
    float q1 = qr[lane], q2 = qr[lane+32];
    qr[lane]    = q1*c - q2*sn;
    qr[lane+32] = q2*c + q1*sn;

    float* kr = k + (size_t)row * CDK;
    float k1 = kr[lane], k2 = kr[lane+32];
    kr[lane]    = k1*c - k2*sn;
    kr[lane+32] = k2*c + k1*sn;
}

// ---------------------------------------------------------------------------
// Causal flash attention: one CTA per (b, h, 64-row q tile). Online softmax.
// Tiles: QsT[64][68] (k-major), KsT[64][68], Ps[64][68], Vs[64][64].
// ---------------------------------------------------------------------------
#define ATTN_SMEM ((64*68*3 + 64*64) * 4)

__global__ __launch_bounds__(256)
void attn_kernel(const float* __restrict__ Qg, const float* __restrict__ Kg,
                 const float* __restrict__ Vg, float* __restrict__ Og)
{
    extern __shared__ float sm[];
    float* QsT = sm;                // [64][68], QsT[dk][q]
    float* KsT = QsT + 64*68;       // [64][68], KsT[dk][kv]
    float* Ps  = KsT + 64*68;       // [64][68], Ps[q][kv]
    float* Vs  = Ps  + 64*68;       // [64][64], Vs[kv][d]

    const int qt = gridDim.x - 1 - blockIdx.x;   // heavy tiles launch first
    const int h  = blockIdx.y, b = blockIdx.z;
    const int bh = b * CH + h;
    const float* Q = Qg + (size_t)bh * CS * CDK;
    const float* K = Kg + (size_t)bh * CS * CDK;
    const float* V = Vg + (size_t)bh * CS * CDK;

    const int tid = threadIdx.x;
    const int tx = tid & 15, ty = tid >> 4;
    const int q0 = qt * 64;

    // Load Q tile, transposed into smem
    #pragma unroll
    for (int t = 0; t < 4; t++) {
        int f = tid + (t << 8);      // 0..1023
        int row = f >> 4;            // 0..63
        int c4  = (f & 15) << 2;     // 0..60
        float4 v = *(const float4*)(Q + (size_t)(q0 + row) * CDK + c4);
        QsT[(c4+0)*68 + row] = v.x;
        QsT[(c4+1)*68 + row] = v.y;
        QsT[(c4+2)*68 + row] = v.z;
        QsT[(c4+3)*68 + row] = v.w;
    }

    float o[4][4] = {};
    float mrow[4], lrow[4];
    #pragma unroll
    for (int i = 0; i < 4; i++) { mrow[i] = -1e30f; lrow[i] = 0.f; }

    for (int jt = 0; jt <= qt; jt++) {
        const int kv0 = jt * 64;
        __syncthreads();   // previous iteration's P@V must finish before reload
        #pragma unroll
        for (int t = 0; t < 4; t++) {
            int f = tid + (t << 8);
            int row = f >> 4;
            int c4  = (f & 15) << 2;
            float4 kvv = *(const float4*)(K + (size_t)(kv0 + row) * CDK + c4);
            KsT[(c4+0)*68 + row] = kvv.x;
            KsT[(c4+1)*68 + row] = kvv.y;
            KsT[(c4+2)*68 + row] = kvv.z;
            KsT[(c4+3)*68 + row] = kvv.w;
            float4 vv = *(const float4*)(V + (size_t)(kv0 + row) * CDK + c4);
            *(float4*)(Vs + row*64 + c4) = vv;
        }
        __syncthreads();

        // scores S = Q K^T (4x4 per thread)
        float s[4][4] = {};
        #pragma unroll 8
        for (int k = 0; k < 64; k++) {
            float4 a  = *(float4*)(QsT + k*68 + ty*4);
            float4 bb = *(float4*)(KsT + k*68 + tx*4);
            float av[4] = {a.x, a.y, a.z, a.w};
            float bvv[4] = {bb.x, bb.y, bb.z, bb.w};
            #pragma unroll
            for (int i = 0; i < 4; i++)
                #pragma unroll
                for (int j = 0; j < 4; j++)
                    s[i][j] = fmaf(av[i], bvv[j], s[i][j]);
        }

        const bool diag = (jt == qt);
        #pragma unroll
        for (int i = 0; i < 4; i++) {
            int ql = ty*4 + i;
            float sv[4];
            #pragma unroll
            for (int j = 0; j < 4; j++) {
                float val = s[i][j] * 0.125f;           // 1/sqrt(64)
                if (diag && (tx*4 + j > ql)) val = -1e30f;
                sv[j] = val;
            }
            float mx = fmaxf(fmaxf(sv[0], sv[1]), fmaxf(sv[2], sv[3]));
            #pragma unroll
            for (int d = 8; d >= 1; d >>= 1)
                mx = fmaxf(mx, __shfl_xor_sync(0xffffffffu, mx, d));
            float newm = fmaxf(mrow[i], mx);
            float fac = __expf(mrow[i] - newm);
            float sum = 0.f;
            #pragma unroll
            for (int j = 0; j < 4; j++) {
                float p = __expf(sv[j] - newm);
                sv[j] = p;
                sum += p;
            }
            #pragma unroll
            for (int d = 8; d >= 1; d >>= 1)
                sum += __shfl_xor_sync(0xffffffffu, sum, d);
            lrow[i] = lrow[i]*fac + sum;
            mrow[i] = newm;
            #pragma unroll
            for (int j = 0; j < 4; j++) o[i][j] *= fac;
            *(float4*)(Ps + (ty*4+i)*68 + tx*4) = make_float4(sv[0], sv[1], sv[2], sv[3]);
        }
        __syncthreads();

        // O += P @ V
        #pragma unroll 8
        for (int kv = 0; kv < 64; kv++) {
            float4 v = *(float4*)(Vs + kv*64 + tx*4);
            #pragma unroll
            for (int i = 0; i < 4; i++) {
                float p = Ps[(ty*4+i)*68 + kv];
                o[i][0] = fmaf(p, v.x, o[i][0]);
                o[i][1] = fmaf(p, v.y, o[i][1]);
                o[i][2] = fmaf(p, v.z, o[i][2]);
                o[i][3] = fmaf(p, v.w, o[i][3]);
            }
        }
    }

    // normalize + write to [B,S,D] layout for the output projection
    #pragma unroll
    for (int i = 0; i < 4; i++) {
        float inv = 1.f / lrow[i];
        int qg = q0 + ty*4 + i;
        float4 r = make_float4(o[i][0]*inv, o[i][1]*inv, o[i][2]*inv, o[i][3]*inv);
        *(float4*)(Og + ((size_t)(b*CS + qg) * CD) + h*CDK + tx*4) = r;
    }
}

// ---------------------------------------------------------------------------
extern "C" void kernel_launch(void* const* d_in, const int* in_sizes, int n_in,
                              void* d_out, int out_size)
{
    const float* x  = (const float*)d_in[0];
    // d_in[1] = mask (causal triu(k=1) by construction; handled analytically)
    const float* Wq = (const float*)d_in[2];
    const float* bq = (const float*)d_in[3];
    const float* Wk = (const float*)d_in[4];
    const float* bk = (const float*)d_in[5];
    const float* Wv = (const float*)d_in[6];
    const float* bv = (const float*)d_in[7];
    const float* Wo = (const float*)d_in[8];
    const float* bo = (const float*)d_in[9];
    float* out = (float*)d_out;

    float *qp, *kp, *vp, *ap;
    cudaGetSymbolAddress((void**)&qp, g_q);
    cudaGetSymbolAddress((void**)&kp, g_k);
    cudaGetSymbolAddress((void**)&vp, g_v);
    cudaGetSymbolAddress((void**)&ap, g_attn);

    cudaFuncSetAttribute(attn_kernel, cudaFuncAttributeMaxDynamicSharedMemorySize, ATTN_SMEM);

    dim3 gb(256);
    dim3 gg(CD/128, CM/128);   // (8, 32)

    trig_kernel<<<(CS*32)/256, 256>>>();
    gemm128<1><<<gg, gb>>>(x, Wq, bq, qp);
    gemm128<1><<<gg, gb>>>(x, Wk, bk, kp);
    gemm128<1><<<gg, gb>>>(x, Wv, bv, vp);
    rope_kernel<<<(CB*CH*CS*32)/256, 256>>>(qp, kp);
    attn_kernel<<<dim3(CS/64, CH, CB), 256, ATTN_SMEM>>>(qp, kp, vp, ap);
    gemm128<0><<<gg, gb>>>(ap, Wo, bo, out);
}

// round 3
// speedup vs baseline: 1.4449x; 1.4449x over previous
#include <cuda_runtime.h>
#include <cuda_bf16.h>
#include <math.h>
#include <stdint.h>

#define CB 2
#define CS 2048
#define CD 1024
#define CH 16
#define CDK 64
#define CM (CB*CS)   // 4096

// ---------------------------------------------------------------------------
// Scratch (__device__ globals; allocation-free rule)
// ---------------------------------------------------------------------------
__device__ float g_q[CB*CH*CS*CDK];
__device__ float g_k[CB*CH*CS*CDK];
__device__ float g_v[CB*CH*CS*CDK];
__device__ float g_trig[CS*32*2];
__device__ __nv_bfloat16 g_xh[CM*CD], g_xl[CM*CD];          // x split
__device__ __nv_bfloat16 g_wh[4][CD*CD], g_wl[4][CD*CD];    // W^T split (q,k,v,o)
__device__ __nv_bfloat16 g_ah[CM*CD], g_al[CM*CD];          // attn out split

// ---------------------------------------------------------------------------
// Helpers
// ---------------------------------------------------------------------------
__device__ __forceinline__ uint32_t smem_u32(const void* p) {
    uint32_t a;
    asm("{ .reg .u64 t; cvta.to.shared.u64 t, %1; cvt.u32.u64 %0, t; }" : "=r"(a) : "l"(p));
    return a;
}

__device__ __forceinline__ void cpa16(uint32_t s, const void* g)
{
    asm volatile("cp.async.cg.shared.global [%0], [%1], 16;"
                 :: "r"(s), "l"(__cvta_generic_to_global(g)) : "memory");
}

__device__ __forceinline__ void ldsm4(uint32_t* r, uint32_t addr)
{
    asm volatile("ldmatrix.sync.aligned.m8n8.x4.shared.b16 {%0,%1,%2,%3}, [%4];"
                 : "=r"(r[0]), "=r"(r[1]), "=r"(r[2]), "=r"(r[3]) : "r"(addr));
}

__device__ __forceinline__ void mma_bf16(float* c, const uint32_t* a, const uint32_t* b)
{
    asm volatile("mma.sync.aligned.m16n8k16.row.col.f32.bf16.bf16.f32 "
                 "{%0,%1,%2,%3}, {%4,%5,%6,%7}, {%8,%9}, {%0,%1,%2,%3};"
                 : "+f"(c[0]), "+f"(c[1]), "+f"(c[2]), "+f"(c[3])
                 : "r"(a[0]), "r"(a[1]), "r"(a[2]), "r"(a[3]), "r"(b[0]), "r"(b[1]));
}

__device__ __forceinline__ void split2(float x, __nv_bfloat16& h, __nv_bfloat16& l)
{
    h = __float2bfloat16(x);
    l = __float2bfloat16(x - __bfloat162float(h));
}

// ---------------------------------------------------------------------------
// Prep kernels
// ---------------------------------------------------------------------------
__global__ void trig_kernel()
{
    int t = blockIdx.x * 256 + threadIdx.x;  // 0..65535
    int s = t >> 5, i = t & 31;
    double theta = exp((double)i * (-log(10000.0) / 32.0));
    double a = (double)s * theta;
    g_trig[t*2]   = (float)cos(a);
    g_trig[t*2+1] = (float)sin(a);
}

__global__ void split_kernel(const float* __restrict__ src,
                             __nv_bfloat16* __restrict__ hi, __nv_bfloat16* __restrict__ lo)
{
    int i = (blockIdx.x * 256 + threadIdx.x) * 4;
    float4 v = *(const float4*)(src + i);
    __nv_bfloat16 h[4], l[4];
    split2(v.x, h[0], l[0]); split2(v.y, h[1], l[1]);
    split2(v.z, h[2], l[2]); split2(v.w, h[3], l[3]);
    *(__nv_bfloat162*)(hi + i)     = __halves2bfloat162(h[0], h[1]);
    *(__nv_bfloat162*)(hi + i + 2) = __halves2bfloat162(h[2], h[3]);
    *(__nv_bfloat162*)(lo + i)     = __halves2bfloat162(l[0], l[1]);
    *(__nv_bfloat162*)(lo + i + 2) = __halves2bfloat162(l[2], l[3]);
}

// W[k][n] -> out[n][k] transposed split (B operand: N-major rows of K)
__global__ void wsplit_kernel(const float* __restrict__ W,
                              __nv_bfloat16* __restrict__ hi, __nv_bfloat16* __restrict__ lo)
{
    __shared__ float t[32][33];
    int bx = blockIdx.x * 32, by = blockIdx.y * 32;
    int tx = threadIdx.x & 31, ty = threadIdx.x >> 5;
    #pragma unroll
    for (int i = 0; i < 4; i++)
        t[ty + 8*i][tx] = W[(size_t)(by + ty + 8*i) * CD + bx + tx];
    __syncthreads();
    #pragma unroll
    for (int i = 0; i < 4; i++) {
        float x = t[tx][ty + 8*i];    // = W[by+tx][bx+ty+8i]
        __nv_bfloat16 h, l;
        split2(x, h, l);
        size_t o = (size_t)(bx + ty + 8*i) * CD + by + tx;
        hi[o] = h; lo[o] = l;
    }
}

// ---------------------------------------------------------------------------
// Split-bf16 tensor-core GEMM via mma.sync (HMMA path, no 'a' PTX features)
// C[4096,1024] = A[M,K] @ B[N,K]^T + bias
// CTA 128x128, BK=64, 3-stage cp.async pipeline.
// Warp grid 4(m) x 2(n): warp tile 32x64. Per warp: 2 m16 x 8 n8 tiles.
// Smem rows padded: 64 bf16 data in 72-bf16 (144B) stride -> ldmatrix conflict-free.
// ---------------------------------------------------------------------------
#define ASTRIDE 144
#define MATB (128*144)          // 18432 bytes per matrix tile
#define BUFB (4*MATB)           // Ah, Al, Bh, Bl
#define NSTAGE 3
#define GEMM_SMEM (NSTAGE*BUFB) // 221184

struct GArgs {
    const __nv_bfloat16 *Ah, *Al, *Bh, *Bl;
    int m0, n0, tid;
    uint32_t s0;
};

__device__ __forceinline__ void issue_chunk(const GArgs& a, int chunk)
{
    int k0 = chunk << 6;
    uint32_t base = a.s0 + (chunk % NSTAGE) * BUFB;
    #pragma unroll
    for (int it = 0; it < 4; it++) {
        int c = a.tid + (it << 8);       // 0..1023
        int row = c >> 3, seg = c & 7;
        uint32_t so = row * ASTRIDE + (seg << 4);
        size_t ga = (size_t)(a.m0 + row) * CD + k0 + (seg << 3);
        size_t gb = (size_t)(a.n0 + row) * CD + k0 + (seg << 3);
        cpa16(base          + so, a.Ah + ga);
        cpa16(base +   MATB + so, a.Al + ga);
        cpa16(base + 2*MATB + so, a.Bh + gb);
        cpa16(base + 3*MATB + so, a.Bl + gb);
    }
    asm volatile("cp.async.commit_group;" ::: "memory");
}

// QKV fused kernel: blockIdx.z selects (W, bias, dst); rope on z<2.
__global__ __launch_bounds__(256)
void gemm_qkv(const __nv_bfloat16* __restrict__ Ah, const __nv_bfloat16* __restrict__ Al,
              const __nv_bfloat16* __restrict__ Wh, const __nv_bfloat16* __restrict__ Wl,
              const float* __restrict__ bq, const float* __restrict__ bk,
              const float* __restrict__ bv,
              float* __restrict__ Dq, float* __restrict__ Dk, float* __restrict__ Dv)
{
    extern __shared__ char smem[];
    const uint32_t s0 = smem_u32(smem);
    const int tid = threadIdx.x, wid = tid >> 5, lane = tid & 31;
    const int wm = wid & 3, wn = wid >> 2;
    const int m0 = blockIdx.y << 7, n0 = blockIdx.x << 7;
    const int z  = blockIdx.z;

    const __nv_bfloat16* Bh = Wh + (size_t)z * CD * CD;
    const __nv_bfloat16* Bl = Wl + (size_t)z * CD * CD;
    const float* bias = (z == 0) ? bq : (z == 1) ? bk : bv;
    float* C = (z == 0) ? Dq : (z == 1) ? Dk : Dv;
    const bool rope = (z < 2);

    GArgs ga{Ah, Al, Bh, Bl, m0, n0, tid, s0};

    float acc[2][8][4];
    #pragma unroll
    for (int i = 0; i < 2; i++)
        #pragma unroll
        for (int j = 0; j < 8; j++)
            #pragma unroll
            for (int r = 0; r < 4; r++) acc[i][j][r] = 0.f;

    issue_chunk(ga, 0);
    issue_chunk(ga, 1);

    // per-lane ldmatrix base addresses (relative to buffer base)
    const uint32_t a_off = (wm*32 + (lane & 15)) * ASTRIDE + ((lane >> 4) << 4);
    const uint32_t b_off = 2*MATB +
        (wn*64 + (lane & 7) + ((lane >> 4) << 3)) * ASTRIDE + (((lane >> 3) & 1) << 4);

    for (int i = 0; i < 16; i++) {
        if (i < 15) asm volatile("cp.async.wait_group 1;" ::: "memory");
        else        asm volatile("cp.async.wait_group 0;" ::: "memory");
        __syncthreads();
        if (i + 2 < 16) issue_chunk(ga, i + 2);

        uint32_t buf = s0 + (i % NSTAGE) * BUFB;
        #pragma unroll
        for (int ks = 0; ks < 4; ks++) {
            uint32_t ah[2][4], al[2][4];
            #pragma unroll
            for (int tm = 0; tm < 2; tm++) {
                uint32_t ad = buf + a_off + tm*16*ASTRIDE + ks*32;
                ldsm4(ah[tm], ad);
                ldsm4(al[tm], ad + MATB);
            }
            #pragma unroll
            for (int tp = 0; tp < 4; tp++) {
                uint32_t bd = buf + b_off + tp*16*ASTRIDE + ks*32;
                uint32_t bh4[4], bl4[4];
                ldsm4(bh4, bd);
                ldsm4(bl4, bd + MATB);
                #pragma unroll
                for (int half = 0; half < 2; half++) {
                    int tn = tp*2 + half;
                    #pragma unroll
                    for (int tm = 0; tm < 2; tm++) {
                        mma_bf16(acc[tm][tn], ah[tm], bh4 + half*2);
                        mma_bf16(acc[tm][tn], ah[tm], bl4 + half*2);
                        mma_bf16(acc[tm][tn], al[tm], bh4 + half*2);
                    }
                }
            }
        }
        __syncthreads();
    }

    // ---- epilogue: bias, rope, scatter to [B,H,S,DK] ----
    #pragma unroll
    for (int tm = 0; tm < 2; tm++) {
        #pragma unroll
        for (int tn = 0; tn < 8; tn++) {
            int col = n0 + wn*64 + tn*8 + (lane & 3)*2;
            float b0 = bias[col], b1 = bias[col+1];
            acc[tm][tn][0] += b0; acc[tm][tn][1] += b1;
            acc[tm][tn][2] += b0; acc[tm][tn][3] += b1;
        }
    }

    if (rope) {
        #pragma unroll
        for (int tm = 0; tm < 2; tm++) {
            #pragma unroll
            for (int tn = 0; tn < 4; tn++) {      // p in [0,32): partner tn+4
                #pragma unroll
                for (int r = 0; r < 4; r++) {
                    int row = m0 + wm*32 + tm*16 + (lane >> 2) + (r >> 1)*8;
                    int s   = row & (CS - 1);
                    int p   = tn*8 + (lane & 3)*2 + (r & 1);
                    float cc = g_trig[(s*32 + p)*2];
                    float sn = g_trig[(s*32 + p)*2 + 1];
                    float lo = acc[tm][tn][r], hi = acc[tm][tn+4][r];
                    acc[tm][tn][r]   = lo*cc - hi*sn;
                    acc[tm][tn+4][r] = hi*cc + lo*sn;
                }
            }
        }
    }

    #pragma unroll
    for (int tm = 0; tm < 2; tm++) {
        #pragma unroll
        for (int tn = 0; tn < 8; tn++) {
            int col = n0 + wn*64 + tn*8 + (lane & 3)*2;
            int h_ = col >> 6, dk = col & 63;
            #pragma unroll
            for (int rh = 0; rh < 2; rh++) {
                int row = m0 + wm*32 + tm*16 + (lane >> 2) + rh*8;
                int b_ = row >> 11, s_ = row & (CS - 1);
                float* dst = C + ((size_t)((b_*CH + h_)*CS + s_)) * CDK + dk;
                *(float2*)dst = make_float2(acc[tm][tn][rh*2], acc[tm][tn][rh*2+1]);
            }
        }
    }
}

// Output projection: row-major C, no rope.
__global__ __launch_bounds__(256)
void gemm_o(const __nv_bfloat16* __restrict__ Ah, const __nv_bfloat16* __restrict__ Al,
            const __nv_bfloat16* __restrict__ Bh, const __nv_bfloat16* __restrict__ Bl,
            const float* __restrict__ bias, float* __restrict__ C)
{
    extern __shared__ char smem[];
    const uint32_t s0 = smem_u32(smem);
    const int tid = threadIdx.x, wid = tid >> 5, lane = tid & 31;
    const int wm = wid & 3, wn = wid >> 2;
    const int m0 = blockIdx.y << 7, n0 = blockIdx.x << 7;

    GArgs ga{Ah, Al, Bh, Bl, m0, n0, tid, s0};

    float acc[2][8][4];
    #pragma unroll
    for (int i = 0; i < 2; i++)
        #pragma unroll
        for (int j = 0; j < 8; j++)
            #pragma unroll
            for (int r = 0; r < 4; r++) acc[i][j][r] = 0.f;

    issue_chunk(ga, 0);
    issue_chunk(ga, 1);

    const uint32_t a_off = (wm*32 + (lane & 15)) * ASTRIDE + ((lane >> 4) << 4);
    const uint32_t b_off = 2*MATB +
        (wn*64 + (lane & 7) + ((lane >> 4) << 3)) * ASTRIDE + (((lane >> 3) & 1) << 4);

    for (int i = 0; i < 16; i++) {
        if (i < 15) asm volatile("cp.async.wait_group 1;" ::: "memory");
        else        asm volatile("cp.async.wait_group 0;" ::: "memory");
        __syncthreads();
        if (i + 2 < 16) issue_chunk(ga, i + 2);

        uint32_t buf = s0 + (i % NSTAGE) * BUFB;
        #pragma unroll
        for (int ks = 0; ks < 4; ks++) {
            uint32_t ah[2][4], al[2][4];
            #pragma unroll
            for (int tm = 0; tm < 2; tm++) {
                uint32_t ad = buf + a_off + tm*16*ASTRIDE + ks*32;
                ldsm4(ah[tm], ad);
                ldsm4(al[tm], ad + MATB);
            }
            #pragma unroll
            for (int tp = 0; tp < 4; tp++) {
                uint32_t bd = buf + b_off + tp*16*ASTRIDE + ks*32;
                uint32_t bh4[4], bl4[4];
                ldsm4(bh4, bd);
                ldsm4(bl4, bd + MATB);
                #pragma unroll
                for (int half = 0; half < 2; half++) {
                    int tn = tp*2 + half;
                    #pragma unroll
                    for (int tm = 0; tm < 2; tm++) {
                        mma_bf16(acc[tm][tn], ah[tm], bh4 + half*2);
                        mma_bf16(acc[tm][tn], ah[tm], bl4 + half*2);
                        mma_bf16(acc[tm][tn], al[tm], bh4 + half*2);
                    }
                }
            }
        }
        __syncthreads();
    }

    #pragma unroll
    for (int tm = 0; tm < 2; tm++) {
        #pragma unroll
        for (int tn = 0; tn < 8; tn++) {
            int col = n0 + wn*64 + tn*8 + (lane & 3)*2;
            float b0 = bias[col], b1 = bias[col+1];
            #pragma unroll
            for (int rh = 0; rh < 2; rh++) {
                int row = m0 + wm*32 + tm*16 + (lane >> 2) + rh*8;
                float* dst = C + (size_t)row * CD + col;
                *(float2*)dst = make_float2(acc[tm][tn][rh*2] + b0,
                                            acc[tm][tn][rh*2+1] + b1);
            }
        }
    }
}

// ---------------------------------------------------------------------------
// Causal flash attention (SIMT fp32); epilogue emits split bf16 for O-GEMM
// ---------------------------------------------------------------------------
#define ATTN_SMEM ((64*68*3 + 64*64) * 4)

__global__ __launch_bounds__(256)
void attn_kernel(const float* __restrict__ Qg, const float* __restrict__ Kg,
                 const float* __restrict__ Vg,
                 __nv_bfloat16* __restrict__ Oh, __nv_bfloat16* __restrict__ Ol)
{
    extern __shared__ float sm[];
    float* QsT = sm;
    float* KsT = QsT + 64*68;
    float* Ps  = KsT + 64*68;
    float* Vs  = Ps  + 64*68;

    const int qt = gridDim.x - 1 - blockIdx.x;
    const int h  = blockIdx.y, b = blockIdx.z;
    const int bh = b * CH + h;
    const float* Q = Qg + (size_t)bh * CS * CDK;
    const float* K = Kg + (size_t)bh * CS * CDK;
    const float* V = Vg + (size_t)bh * CS * CDK;

    const int tid = threadIdx.x;
    const int tx = tid & 15, ty = tid >> 4;
    const int q0 = qt * 64;

    #pragma unroll
    for (int t = 0; t < 4; t++) {
        int f = tid + (t << 8);
        int row = f >> 4;
        int c4  = (f & 15) << 2;
        float4 v = *(const float4*)(Q + (size_t)(q0 + row) * CDK + c4);
        QsT[(c4+0)*68 + row] = v.x;
        QsT[(c4+1)*68 + row] = v.y;
        QsT[(c4+2)*68 + row] = v.z;
        QsT[(c4+3)*68 + row] = v.w;
    }

    float o[4][4] = {};
    float mrow[4], lrow[4];
    #pragma unroll
    for (int i = 0; i < 4; i++) { mrow[i] = -1e30f; lrow[i] = 0.f; }

    for (int jt = 0; jt <= qt; jt++) {
        const int kv0 = jt * 64;
        __syncthreads();
        #pragma unroll
        for (int t = 0; t < 4; t++) {
            int f = tid + (t << 8);
            int row = f >> 4;
            int c4  = (f & 15) << 2;
            float4 kvv = *(const float4*)(K + (size_t)(kv0 + row) * CDK + c4);
            KsT[(c4+0)*68 + row] = kvv.x;
            KsT[(c4+1)*68 + row] = kvv.y;
            KsT[(c4+2)*68 + row] = kvv.z;
            KsT[(c4+3)*68 + row] = kvv.w;
            float4 vv = *(const float4*)(V + (size_t)(kv0 + row) * CDK + c4);
            *(float4*)(Vs + row*64 + c4) = vv;
        }
        __syncthreads();

        float s[4][4] = {};
        #pragma unroll 8
        for (int k = 0; k < 64; k++) {
            float4 a  = *(float4*)(QsT + k*68 + ty*4);
            float4 bb = *(float4*)(KsT + k*68 + tx*4);
            float av[4]  = {a.x, a.y, a.z, a.w};
            float bvv[4] = {bb.x, bb.y, bb.z, bb.w};
            #pragma unroll
            for (int i = 0; i < 4; i++)
                #pragma unroll
                for (int j = 0; j < 4; j++)
                    s[i][j] = fmaf(av[i], bvv[j], s[i][j]);
        }

        const bool diag = (jt == qt);
        #pragma unroll
        for (int i = 0; i < 4; i++) {
            int ql = ty*4 + i;
            float sv[4];
            #pragma unroll
            for (int j = 0; j < 4; j++) {
                float val = s[i][j] * 0.125f;
                if (diag && (tx*4 + j > ql)) val = -1e30f;
                sv[j] = val;
            }
            float mx = fmaxf(fmaxf(sv[0], sv[1]), fmaxf(sv[2], sv[3]));
            #pragma unroll
            for (int d = 8; d >= 1; d >>= 1)
                mx = fmaxf(mx, __shfl_xor_sync(0xffffffffu, mx, d));
            float newm = fmaxf(mrow[i], mx);
            float fac = __expf(mrow[i] - newm);
            float sum = 0.f;
            #pragma unroll
            for (int j = 0; j < 4; j++) {
                float p = __expf(sv[j] - newm);
                sv[j] = p;
                sum += p;
            }
            #pragma unroll
            for (int d = 8; d >= 1; d >>= 1)
                sum += __shfl_xor_sync(0xffffffffu, sum, d);
            lrow[i] = lrow[i]*fac + sum;
            mrow[i] = newm;
            #pragma unroll
            for (int j = 0; j < 4; j++) o[i][j] *= fac;
            *(float4*)(Ps + (ty*4+i)*68 + tx*4) = make_float4(sv[0], sv[1], sv[2], sv[3]);
        }
        __syncthreads();

        #pragma unroll 8
        for (int kv = 0; kv < 64; kv++) {
            float4 v = *(float4*)(Vs + kv*64 + tx*4);
            #pragma unroll
            for (int i = 0; i < 4; i++) {
                float p = Ps[(ty*4+i)*68 + kv];
                o[i][0] = fmaf(p, v.x, o[i][0]);
                o[i][1] = fmaf(p, v.y, o[i][1]);
                o[i][2] = fmaf(p, v.z, o[i][2]);
                o[i][3] = fmaf(p, v.w, o[i][3]);
            }
        }
    }

    #pragma unroll
    for (int i = 0; i < 4; i++) {
        float inv = 1.f / lrow[i];
        int qg = q0 + ty*4 + i;
        float vals[4] = {o[i][0]*inv, o[i][1]*inv, o[i][2]*inv, o[i][3]*inv};
        __nv_bfloat16 hh[4], ll[4];
        #pragma unroll
        for (int j = 0; j < 4; j++) split2(vals[j], hh[j], ll[j]);
        size_t base = (size_t)(b*CS + qg) * CD + h*CDK + tx*4;
        *(__nv_bfloat162*)(Oh + base)     = __halves2bfloat162(hh[0], hh[1]);
        *(__nv_bfloat162*)(Oh + base + 2) = __halves2bfloat162(hh[2], hh[3]);
        *(__nv_bfloat162*)(Ol + base)     = __halves2bfloat162(ll[0], ll[1]);
        *(__nv_bfloat162*)(Ol + base + 2) = __halves2bfloat162(ll[2], ll[3]);
    }
}

// ---------------------------------------------------------------------------
extern "C" void kernel_launch(void* const* d_in, const int* in_sizes, int n_in,
                              void* d_out, int out_size)
{
    const float* x  = (const float*)d_in[0];
    // d_in[1] = mask (causal triu(k=1), handled analytically)
    const float* Wq = (const float*)d_in[2];
    const float* bq = (const float*)d_in[3];
    const float* Wk = (const float*)d_in[4];
    const float* bk = (const float*)d_in[5];
    const float* Wv = (const float*)d_in[6];
    const float* bv = (const float*)d_in[7];
    const float* Wo = (const float*)d_in[8];
    const float* bo = (const float*)d_in[9];
    float* out = (float*)d_out;

    float *qp, *kp, *vp;
    __nv_bfloat16 *xh, *xl, *wh, *wl, *ah, *al;
    cudaGetSymbolAddress((void**)&qp, g_q);
    cudaGetSymbolAddress((void**)&kp, g_k);
    cudaGetSymbolAddress((void**)&vp, g_v);
    cudaGetSymbolAddress((void**)&xh, g_xh);
    cudaGetSymbolAddress((void**)&xl, g_xl);
    cudaGetSymbolAddress((void**)&wh, g_wh);
    cudaGetSymbolAddress((void**)&wl, g_wl);
    cudaGetSymbolAddress((void**)&ah, g_ah);
    cudaGetSymbolAddress((void**)&al, g_al);

    cudaFuncSetAttribute(attn_kernel, cudaFuncAttributeMaxDynamicSharedMemorySize, ATTN_SMEM);
    cudaFuncSetAttribute(gemm_qkv, cudaFuncAttributeMaxDynamicSharedMemorySize, GEMM_SMEM);
    cudaFuncSetAttribute(gemm_o,   cudaFuncAttributeMaxDynamicSharedMemorySize, GEMM_SMEM);

    trig_kernel<<<256, 256>>>();
    split_kernel<<<(CM*CD)/1024, 256>>>(x, xh, xl);
    wsplit_kernel<<<dim3(32,32), 256>>>(Wq, wh + 0*CD*CD, wl + 0*CD*CD);
    wsplit_kernel<<<dim3(32,32), 256>>>(Wk, wh + 1*CD*CD, wl + 1*CD*CD);
    wsplit_kernel<<<dim3(32,32), 256>>>(Wv, wh + 2*CD*CD, wl + 2*CD*CD);
    wsplit_kernel<<<dim3(32,32), 256>>>(Wo, wh + 3*CD*CD, wl + 3*CD*CD);

    gemm_qkv<<<dim3(CD/128, CM/128, 3), 256, GEMM_SMEM>>>(
        xh, xl, wh, wl, bq, bk, bv, qp, kp, vp);

    attn_kernel<<<dim3(CS/64, CH, CB), 256, ATTN_SMEM>>>(qp, kp, vp, ah, al);

    gemm_o<<<dim3(CD/128, CM/128), 256, GEMM_SMEM>>>(
        ah, al, wh + 3*CD*CD, wl + 3*CD*CD, bo, out);
}

// round 4
// speedup vs baseline: 2.6788x; 1.8540x over previous
#include <cuda_runtime.h>
#include <cuda_bf16.h>
#include <math.h>
#include <stdint.h>

#define CB 2
#define CS 2048
#define CD 1024
#define CH 16
#define CDK 64
#define CM (CB*CS)   // 4096

// ---------------------------------------------------------------------------
// Scratch (__device__ globals; allocation-free rule)
// ---------------------------------------------------------------------------
__device__ float g_trig[CS*32*2];
__device__ __nv_bfloat16 g_xh[CM*CD], g_xl[CM*CD];          // x split
__device__ __nv_bfloat16 g_wh[4][CD*CD], g_wl[4][CD*CD];    // W^T split (q,k,v,o)
__device__ __nv_bfloat16 g_qh[CB*CH*CS*CDK], g_ql[CB*CH*CS*CDK];
__device__ __nv_bfloat16 g_kh[CB*CH*CS*CDK], g_kl[CB*CH*CS*CDK];
__device__ __nv_bfloat16 g_vh[CB*CH*CS*CDK], g_vl[CB*CH*CS*CDK];
__device__ __nv_bfloat16 g_ah[CM*CD], g_al[CM*CD];          // attn out split

// ---------------------------------------------------------------------------
// Helpers
// ---------------------------------------------------------------------------
__device__ __forceinline__ uint32_t smem_u32(const void* p) {
    uint32_t a;
    asm("{ .reg .u64 t; cvta.to.shared.u64 t, %1; cvt.u32.u64 %0, t; }" : "=r"(a) : "l"(p));
    return a;
}

__device__ __forceinline__ void cpa16(uint32_t s, const void* g)
{
    asm volatile("cp.async.cg.shared.global [%0], [%1], 16;"
                 :: "r"(s), "l"(__cvta_generic_to_global(g)) : "memory");
}

__device__ __forceinline__ void ldsm4(uint32_t* r, uint32_t addr)
{
    asm volatile("ldmatrix.sync.aligned.m8n8.x4.shared.b16 {%0,%1,%2,%3}, [%4];"
                 : "=r"(r[0]), "=r"(r[1]), "=r"(r[2]), "=r"(r[3]) : "r"(addr));
}

__device__ __forceinline__ void ldsm4t(uint32_t* r, uint32_t addr)
{
    asm volatile("ldmatrix.sync.aligned.m8n8.x4.trans.shared.b16 {%0,%1,%2,%3}, [%4];"
                 : "=r"(r[0]), "=r"(r[1]), "=r"(r[2]), "=r"(r[3]) : "r"(addr));
}

__device__ __forceinline__ void mma_bf16(float* c, const uint32_t* a, const uint32_t* b)
{
    asm volatile("mma.sync.aligned.m16n8k16.row.col.f32.bf16.bf16.f32 "
                 "{%0,%1,%2,%3}, {%4,%5,%6,%7}, {%8,%9}, {%0,%1,%2,%3};"
                 : "+f"(c[0]), "+f"(c[1]), "+f"(c[2]), "+f"(c[3])
                 : "r"(a[0]), "r"(a[1]), "r"(a[2]), "r"(a[3]), "r"(b[0]), "r"(b[1]));
}

__device__ __forceinline__ void split2(float x, __nv_bfloat16& h, __nv_bfloat16& l)
{
    h = __float2bfloat16(x);
    l = __float2bfloat16(x - __bfloat162float(h));
}

__device__ __forceinline__ uint32_t pack_bf16(__nv_bfloat16 a, __nv_bfloat16 b)
{
    __nv_bfloat162 t = __halves2bfloat162(a, b);
    return *(uint32_t*)&t;
}

// ---------------------------------------------------------------------------
// Prep kernels
// ---------------------------------------------------------------------------
__global__ void trig_kernel()
{
    int t = blockIdx.x * 256 + threadIdx.x;
    int s = t >> 5, i = t & 31;
    double theta = exp((double)i * (-log(10000.0) / 32.0));
    double a = (double)s * theta;
    g_trig[t*2]   = (float)cos(a);
    g_trig[t*2+1] = (float)sin(a);
}

__global__ void split_kernel(const float* __restrict__ src,
                             __nv_bfloat16* __restrict__ hi, __nv_bfloat16* __restrict__ lo)
{
    int i = (blockIdx.x * 256 + threadIdx.x) * 4;
    float4 v = *(const float4*)(src + i);
    __nv_bfloat16 h[4], l[4];
    split2(v.x, h[0], l[0]); split2(v.y, h[1], l[1]);
    split2(v.z, h[2], l[2]); split2(v.w, h[3], l[3]);
    *(__nv_bfloat162*)(hi + i)     = __halves2bfloat162(h[0], h[1]);
    *(__nv_bfloat162*)(hi + i + 2) = __halves2bfloat162(h[2], h[3]);
    *(__nv_bfloat162*)(lo + i)     = __halves2bfloat162(l[0], l[1]);
    *(__nv_bfloat162*)(lo + i + 2) = __halves2bfloat162(l[2], l[3]);
}

__global__ void wsplit_kernel(const float* __restrict__ W,
                              __nv_bfloat16* __restrict__ hi, __nv_bfloat16* __restrict__ lo)
{
    __shared__ float t[32][33];
    int bx = blockIdx.x * 32, by = blockIdx.y * 32;
    int tx = threadIdx.x & 31, ty = threadIdx.x >> 5;
    #pragma unroll
    for (int i = 0; i < 4; i++)
        t[ty + 8*i][tx] = W[(size_t)(by + ty + 8*i) * CD + bx + tx];
    __syncthreads();
    #pragma unroll
    for (int i = 0; i < 4; i++) {
        float x = t[tx][ty + 8*i];
        __nv_bfloat16 h, l;
        split2(x, h, l);
        size_t o = (size_t)(bx + ty + 8*i) * CD + by + tx;
        hi[o] = h; lo[o] = l;
    }
}

// ---------------------------------------------------------------------------
// Split-bf16 tensor-core GEMM via mma.sync
// ---------------------------------------------------------------------------
#define ASTRIDE 144
#define MATB (128*144)
#define BUFB (4*MATB)
#define NSTAGE 3
#define GEMM_SMEM (NSTAGE*BUFB)

struct GArgs {
    const __nv_bfloat16 *Ah, *Al, *Bh, *Bl;
    int m0, n0, tid;
    uint32_t s0;
};

__device__ __forceinline__ void issue_chunk(const GArgs& a, int chunk)
{
    int k0 = chunk << 6;
    uint32_t base = a.s0 + (chunk % NSTAGE) * BUFB;
    #pragma unroll
    for (int it = 0; it < 4; it++) {
        int c = a.tid + (it << 8);
        int row = c >> 3, seg = c & 7;
        uint32_t so = row * ASTRIDE + (seg << 4);
        size_t ga = (size_t)(a.m0 + row) * CD + k0 + (seg << 3);
        size_t gb = (size_t)(a.n0 + row) * CD + k0 + (seg << 3);
        cpa16(base          + so, a.Ah + ga);
        cpa16(base +   MATB + so, a.Al + ga);
        cpa16(base + 2*MATB + so, a.Bh + gb);
        cpa16(base + 3*MATB + so, a.Bl + gb);
    }
    asm volatile("cp.async.commit_group;" ::: "memory");
}

// QKV fused; epilogue: bias, rope (q,k), q-prescale 1/8, split-bf16 scatter [B,H,S,DK]
__global__ __launch_bounds__(256)
void gemm_qkv(const __nv_bfloat16* __restrict__ Ah, const __nv_bfloat16* __restrict__ Al,
              const __nv_bfloat16* __restrict__ Wh, const __nv_bfloat16* __restrict__ Wl,
              const float* __restrict__ bq, const float* __restrict__ bk,
              const float* __restrict__ bv,
              __nv_bfloat16* __restrict__ Qh, __nv_bfloat16* __restrict__ Ql,
              __nv_bfloat16* __restrict__ Kh, __nv_bfloat16* __restrict__ Kl,
              __nv_bfloat16* __restrict__ Vh, __nv_bfloat16* __restrict__ Vl)
{
    extern __shared__ char smem[];
    const uint32_t s0 = smem_u32(smem);
    const int tid = threadIdx.x, wid = tid >> 5, lane = tid & 31;
    const int wm = wid & 3, wn = wid >> 2;
    const int m0 = blockIdx.y << 7, n0 = blockIdx.x << 7;
    const int z  = blockIdx.z;

    const __nv_bfloat16* Bh = Wh + (size_t)z * CD * CD;
    const __nv_bfloat16* Bl = Wl + (size_t)z * CD * CD;
    const float* bias = (z == 0) ? bq : (z == 1) ? bk : bv;
    __nv_bfloat16* Dh = (z == 0) ? Qh : (z == 1) ? Kh : Vh;
    __nv_bfloat16* Dl = (z == 0) ? Ql : (z == 1) ? Kl : Vl;
    const bool rope = (z < 2);
    const float oscale = (z == 0) ? 0.125f : 1.0f;

    GArgs ga{Ah, Al, Bh, Bl, m0, n0, tid, s0};

    float acc[2][8][4];
    #pragma unroll
    for (int i = 0; i < 2; i++)
        #pragma unroll
        for (int j = 0; j < 8; j++)
            #pragma unroll
            for (int r = 0; r < 4; r++) acc[i][j][r] = 0.f;

    issue_chunk(ga, 0);
    issue_chunk(ga, 1);

    const uint32_t a_off = (wm*32 + (lane & 15)) * ASTRIDE + ((lane >> 4) << 4);
    const uint32_t b_off = 2*MATB +
        (wn*64 + (lane & 7) + ((lane >> 4) << 3)) * ASTRIDE + (((lane >> 3) & 1) << 4);

    for (int i = 0; i < 16; i++) {
        if (i < 15) asm volatile("cp.async.wait_group 1;" ::: "memory");
        else        asm volatile("cp.async.wait_group 0;" ::: "memory");
        __syncthreads();
        if (i + 2 < 16) issue_chunk(ga, i + 2);

        uint32_t buf = s0 + (i % NSTAGE) * BUFB;
        #pragma unroll
        for (int ks = 0; ks < 4; ks++) {
            uint32_t ah[2][4], al[2][4];
            #pragma unroll
            for (int tm = 0; tm < 2; tm++) {
                uint32_t ad = buf + a_off + tm*16*ASTRIDE + ks*32;
                ldsm4(ah[tm], ad);
                ldsm4(al[tm], ad + MATB);
            }
            #pragma unroll
            for (int tp = 0; tp < 4; tp++) {
                uint32_t bd = buf + b_off + tp*16*ASTRIDE + ks*32;
                uint32_t bh4[4], bl4[4];
                ldsm4(bh4, bd);
                ldsm4(bl4, bd + MATB);
                #pragma unroll
                for (int half = 0; half < 2; half++) {
                    int tn = tp*2 + half;
                    #pragma unroll
                    for (int tm = 0; tm < 2; tm++) {
                        mma_bf16(acc[tm][tn], ah[tm], bh4 + half*2);
                        mma_bf16(acc[tm][tn], ah[tm], bl4 + half*2);
                        mma_bf16(acc[tm][tn], al[tm], bh4 + half*2);
                    }
                }
            }
        }
        __syncthreads();
    }

    #pragma unroll
    for (int tm = 0; tm < 2; tm++) {
        #pragma unroll
        for (int tn = 0; tn < 8; tn++) {
            int col = n0 + wn*64 + tn*8 + (lane & 3)*2;
            float b0 = bias[col], b1 = bias[col+1];
            acc[tm][tn][0] += b0; acc[tm][tn][1] += b1;
            acc[tm][tn][2] += b0; acc[tm][tn][3] += b1;
        }
    }

    if (rope) {
        #pragma unroll
        for (int tm = 0; tm < 2; tm++) {
            #pragma unroll
            for (int tn = 0; tn < 4; tn++) {
                #pragma unroll
                for (int r = 0; r < 4; r++) {
                    int row = m0 + wm*32 + tm*16 + (lane >> 2) + (r >> 1)*8;
                    int s   = row & (CS - 1);
                    int p   = tn*8 + (lane & 3)*2 + (r & 1);
                    float cc = g_trig[(s*32 + p)*2];
                    float sn = g_trig[(s*32 + p)*2 + 1];
                    float lo = acc[tm][tn][r], hi = acc[tm][tn+4][r];
                    acc[tm][tn][r]   = lo*cc - hi*sn;
                    acc[tm][tn+4][r] = hi*cc + lo*sn;
                }
            }
        }
    }

    #pragma unroll
    for (int tm = 0; tm < 2; tm++) {
        #pragma unroll
        for (int tn = 0; tn < 8; tn++) {
            int col = n0 + wn*64 + tn*8 + (lane & 3)*2;
            int h_ = col >> 6, dk = col & 63;
            #pragma unroll
            for (int rh = 0; rh < 2; rh++) {
                int row = m0 + wm*32 + tm*16 + (lane >> 2) + rh*8;
                int b_ = row >> 11, s_ = row & (CS - 1);
                size_t idx = ((size_t)((b_*CH + h_)*CS + s_)) * CDK + dk;
                float v0 = acc[tm][tn][rh*2]   * oscale;
                float v1 = acc[tm][tn][rh*2+1] * oscale;
                __nv_bfloat16 h0, l0, h1, l1;
                split2(v0, h0, l0);
                split2(v1, h1, l1);
                *(__nv_bfloat162*)(Dh + idx) = __halves2bfloat162(h0, h1);
                *(__nv_bfloat162*)(Dl + idx) = __halves2bfloat162(l0, l1);
            }
        }
    }
}

// Output projection: row-major fp32 C.
__global__ __launch_bounds__(256)
void gemm_o(const __nv_bfloat16* __restrict__ Ah, const __nv_bfloat16* __restrict__ Al,
            const __nv_bfloat16* __restrict__ Bh, const __nv_bfloat16* __restrict__ Bl,
            const float* __restrict__ bias, float* __restrict__ C)
{
    extern __shared__ char smem[];
    const uint32_t s0 = smem_u32(smem);
    const int tid = threadIdx.x, wid = tid >> 5, lane = tid & 31;
    const int wm = wid & 3, wn = wid >> 2;
    const int m0 = blockIdx.y << 7, n0 = blockIdx.x << 7;

    GArgs ga{Ah, Al, Bh, Bl, m0, n0, tid, s0};

    float acc[2][8][4];
    #pragma unroll
    for (int i = 0; i < 2; i++)
        #pragma unroll
        for (int j = 0; j < 8; j++)
            #pragma unroll
            for (int r = 0; r < 4; r++) acc[i][j][r] = 0.f;

    issue_chunk(ga, 0);
    issue_chunk(ga, 1);

    const uint32_t a_off = (wm*32 + (lane & 15)) * ASTRIDE + ((lane >> 4) << 4);
    const uint32_t b_off = 2*MATB +
        (wn*64 + (lane & 7) + ((lane >> 4) << 3)) * ASTRIDE + (((lane >> 3) & 1) << 4);

    for (int i = 0; i < 16; i++) {
        if (i < 15) asm volatile("cp.async.wait_group 1;" ::: "memory");
        else        asm volatile("cp.async.wait_group 0;" ::: "memory");
        __syncthreads();
        if (i + 2 < 16) issue_chunk(ga, i + 2);

        uint32_t buf = s0 + (i % NSTAGE) * BUFB;
        #pragma unroll
        for (int ks = 0; ks < 4; ks++) {
            uint32_t ah[2][4], al[2][4];
            #pragma unroll
            for (int tm = 0; tm < 2; tm++) {
                uint32_t ad = buf + a_off + tm*16*ASTRIDE + ks*32;
                ldsm4(ah[tm], ad);
                ldsm4(al[tm], ad + MATB);
            }
            #pragma unroll
            for (int tp = 0; tp < 4; tp++) {
                uint32_t bd = buf + b_off + tp*16*ASTRIDE + ks*32;
                uint32_t bh4[4], bl4[4];
                ldsm4(bh4, bd);
                ldsm4(bl4, bd + MATB);
                #pragma unroll
                for (int half = 0; half < 2; half++) {
                    int tn = tp*2 + half;
                    #pragma unroll
                    for (int tm = 0; tm < 2; tm++) {
                        mma_bf16(acc[tm][tn], ah[tm], bh4 + half*2);
                        mma_bf16(acc[tm][tn], ah[tm], bl4 + half*2);
                        mma_bf16(acc[tm][tn], al[tm], bh4 + half*2);
                    }
                }
            }
        }
        __syncthreads();
    }

    #pragma unroll
    for (int tm = 0; tm < 2; tm++) {
        #pragma unroll
        for (int tn = 0; tn < 8; tn++) {
            int col = n0 + wn*64 + tn*8 + (lane & 3)*2;
            float b0 = bias[col], b1 = bias[col+1];
            #pragma unroll
            for (int rh = 0; rh < 2; rh++) {
                int row = m0 + wm*32 + tm*16 + (lane >> 2) + rh*8;
                float* dst = C + (size_t)row * CD + col;
                *(float2*)dst = make_float2(acc[tm][tn][rh*2] + b0,
                                            acc[tm][tn][rh*2+1] + b1);
            }
        }
    }
}

// ---------------------------------------------------------------------------
// Tensor-core causal flash attention (mma.sync, split-bf16 everywhere)
// CTA: (b, h, 128-row q-tile). 8 warps x 16 rows. KV tiles of 64, double-buffered.
// Q is pre-scaled by 1/sqrt(DK) in the projection epilogue.
// ---------------------------------------------------------------------------
#define AT_STRIDE 144
#define AT_QMAT (128*AT_STRIDE)     // 18432
#define AT_KMAT (64*AT_STRIDE)      // 9216
#define AT_STAGE (4*AT_KMAT)        // 36864
#define ATTN_SMEM (2*AT_QMAT + 2*AT_STAGE)   // 110592

__global__ __launch_bounds__(256, 1)
void attn_tc(const __nv_bfloat16* __restrict__ Qh, const __nv_bfloat16* __restrict__ Ql,
             const __nv_bfloat16* __restrict__ Kh, const __nv_bfloat16* __restrict__ Kl,
             const __nv_bfloat16* __restrict__ Vh, const __nv_bfloat16* __restrict__ Vl,
             __nv_bfloat16* __restrict__ Oh, __nv_bfloat16* __restrict__ Ol)
{
    extern __shared__ char smem[];
    const uint32_t s0 = smem_u32(smem);
    const int tid = threadIdx.x, w = tid >> 5, lane = tid & 31;

    const int qt = gridDim.x - 1 - blockIdx.x;        // heavy tiles first
    const int h  = blockIdx.y, b = blockIdx.z;
    const size_t g = (size_t)(b * CH + h) * CS * CDK;
    const int q0 = qt * 128;
    const int njt = 2*qt + 2;

    const __nv_bfloat16 *Qhg = Qh + g, *Qlg = Ql + g;
    const __nv_bfloat16 *Khg = Kh + g, *Klg = Kl + g;
    const __nv_bfloat16 *Vhg = Vh + g, *Vlg = Vl + g;

    const uint32_t sQ  = s0;               // Qh then Ql (+AT_QMAT)
    const uint32_t sKV = s0 + 2*AT_QMAT;   // stage: Kh, Kl, Vh, Vl (each AT_KMAT)

    auto issue_kv = [&](int jt) {
        int kv0 = jt * 64;
        uint32_t sb = sKV + (jt & 1) * AT_STAGE;
        #pragma unroll
        for (int it = 0; it < 2; it++) {
            int c = tid + (it << 8);
            int row = c >> 3, seg = c & 7;
            uint32_t so = row * AT_STRIDE + (seg << 4);
            size_t off = (size_t)(kv0 + row) * CDK + (seg << 3);
            cpa16(sb               + so, Khg + off);
            cpa16(sb +   AT_KMAT   + so, Klg + off);
            cpa16(sb + 2*AT_KMAT   + so, Vhg + off);
            cpa16(sb + 3*AT_KMAT   + so, Vlg + off);
        }
        asm volatile("cp.async.commit_group;" ::: "memory");
    };

    // Q loads (grouped with kv tile 0)
    #pragma unroll
    for (int it = 0; it < 4; it++) {
        int c = tid + (it << 8);
        int row = c >> 3, seg = c & 7;
        uint32_t so = row * AT_STRIDE + (seg << 4);
        size_t off = (size_t)(q0 + row) * CDK + (seg << 3);
        cpa16(sQ           + so, Qhg + off);
        cpa16(sQ + AT_QMAT + so, Qlg + off);
    }
    issue_kv(0);        // commits group0 = Q + KV0
    if (njt > 1) issue_kv(1);

    // fragment lane patterns
    const uint32_t q_off = (w*16 + (lane & 15)) * AT_STRIDE + ((lane >> 4) << 4);
    const uint32_t k_pat = ((lane & 7) + ((lane >> 4) << 3)) * AT_STRIDE + (((lane >> 3) & 1) << 4);
    const uint32_t v_pat = ((lane & 7) + (((lane >> 3) & 1) << 3)) * AT_STRIDE + ((lane >> 4) << 4);

    uint32_t qfh[4][4], qfl[4][4];
    float o[8][4];
    #pragma unroll
    for (int j = 0; j < 8; j++)
        #pragma unroll
        for (int r = 0; r < 4; r++) o[j][r] = 0.f;
    float mA = -1e30f, mB = -1e30f, lA = 0.f, lB = 0.f;

    const int rowA_g = q0 + w*16 + (lane >> 2);    // global q row (r<2)
    const int colL   = (lane & 3) * 2;

    for (int jt = 0; jt < njt; jt++) {
        if (jt + 1 < njt) asm volatile("cp.async.wait_group 1;" ::: "memory");
        else              asm volatile("cp.async.wait_group 0;" ::: "memory");
        __syncthreads();

        if (jt == 0) {
            #pragma unroll
            for (int kc = 0; kc < 4; kc++) {
                ldsm4(qfh[kc], sQ + q_off + kc*32);
                ldsm4(qfl[kc], sQ + AT_QMAT + q_off + kc*32);
            }
        }

        const uint32_t sb = sKV + (jt & 1) * AT_STAGE;
        const int kv0 = jt * 64;

        // ---- S = Q K^T (3-term split) ----
        float s[8][4];
        #pragma unroll
        for (int j = 0; j < 8; j++)
            #pragma unroll
            for (int r = 0; r < 4; r++) s[j][r] = 0.f;

        #pragma unroll
        for (int kc = 0; kc < 4; kc++) {
            #pragma unroll
            for (int np = 0; np < 4; np++) {
                uint32_t ad = sb + k_pat + np*16*AT_STRIDE + kc*32;
                uint32_t kh4[4], kl4[4];
                ldsm4(kh4, ad);
                ldsm4(kl4, ad + AT_KMAT);
                #pragma unroll
                for (int half = 0; half < 2; half++) {
                    int tn = np*2 + half;
                    mma_bf16(s[tn], qfh[kc], kh4 + half*2);
                    mma_bf16(s[tn], qfl[kc], kh4 + half*2);
                    mma_bf16(s[tn], qfh[kc], kl4 + half*2);
                }
            }
        }

        // ---- mask + online softmax ----
        if (jt >= 2*qt) {   // diagonal region
            #pragma unroll
            for (int tn = 0; tn < 8; tn++) {
                int col = kv0 + tn*8 + colL;
                if (col     > rowA_g) s[tn][0] = -1e30f;
                if (col + 1 > rowA_g) s[tn][1] = -1e30f;
                if (col     > rowA_g + 8) s[tn][2] = -1e30f;
                if (col + 1 > rowA_g + 8) s[tn][3] = -1e30f;
            }
        }

        float mxA = -1e30f, mxB = -1e30f;
        #pragma unroll
        for (int tn = 0; tn < 8; tn++) {
            mxA = fmaxf(mxA, fmaxf(s[tn][0], s[tn][1]));
            mxB = fmaxf(mxB, fmaxf(s[tn][2], s[tn][3]));
        }
        mxA = fmaxf(mxA, __shfl_xor_sync(0xffffffffu, mxA, 1));
        mxA = fmaxf(mxA, __shfl_xor_sync(0xffffffffu, mxA, 2));
        mxB = fmaxf(mxB, __shfl_xor_sync(0xffffffffu, mxB, 1));
        mxB = fmaxf(mxB, __shfl_xor_sync(0xffffffffu, mxB, 2));

        float nmA = fmaxf(mA, mxA), nmB = fmaxf(mB, mxB);
        float facA = __expf(mA - nmA), facB = __expf(mB - nmB);

        float sumA = 0.f, sumB = 0.f;
        #pragma unroll
        for (int tn = 0; tn < 8; tn++) {
            s[tn][0] = __expf(s[tn][0] - nmA);
            s[tn][1] = __expf(s[tn][1] - nmA);
            s[tn][2] = __expf(s[tn][2] - nmB);
            s[tn][3] = __expf(s[tn][3] - nmB);
            sumA += s[tn][0] + s[tn][1];
            sumB += s[tn][2] + s[tn][3];
        }
        sumA += __shfl_xor_sync(0xffffffffu, sumA, 1);
        sumA += __shfl_xor_sync(0xffffffffu, sumA, 2);
        sumB += __shfl_xor_sync(0xffffffffu, sumB, 1);
        sumB += __shfl_xor_sync(0xffffffffu, sumB, 2);

        lA = lA*facA + sumA;  mA = nmA;
        lB = lB*facB + sumB;  mB = nmB;

        #pragma unroll
        for (int tn = 0; tn < 8; tn++) {
            o[tn][0] *= facA; o[tn][1] *= facA;
            o[tn][2] *= facB; o[tn][3] *= facB;
        }

        // ---- O += P V (3-term split) ----
        #pragma unroll
        for (int kc = 0; kc < 4; kc++) {
            // repack S accumulators (tn=2kc, 2kc+1) as A-fragments (hi, lo)
            uint32_t pah[4], pal[4];
            {
                __nv_bfloat16 h0, l0, h1, l1;
                split2(s[2*kc][0], h0, l0); split2(s[2*kc][1], h1, l1);
                pah[0] = pack_bf16(h0, h1); pal[0] = pack_bf16(l0, l1);
                split2(s[2*kc][2], h0, l0); split2(s[2*kc][3], h1, l1);
                pah[1] = pack_bf16(h0, h1); pal[1] = pack_bf16(l0, l1);
                split2(s[2*kc+1][0], h0, l0); split2(s[2*kc+1][1], h1, l1);
                pah[2] = pack_bf16(h0, h1); pal[2] = pack_bf16(l0, l1);
                split2(s[2*kc+1][2], h0, l0); split2(s[2*kc+1][3], h1, l1);
                pah[3] = pack_bf16(h0, h1); pal[3] = pack_bf16(l0, l1);
            }
            #pragma unroll
            for (int np = 0; np < 4; np++) {
                uint32_t ad = sb + 2*AT_KMAT + v_pat + kc*16*AT_STRIDE + np*32;
                uint32_t vh4[4], vl4[4];
                ldsm4t(vh4, ad);
                ldsm4t(vl4, ad + AT_KMAT);
                #pragma unroll
                for (int half = 0; half < 2; half++) {
                    int tn = np*2 + half;
                    mma_bf16(o[tn], pah, vh4 + half*2);
                    mma_bf16(o[tn], pal, vh4 + half*2);
                    mma_bf16(o[tn], pah, vl4 + half*2);
                }
            }
        }

        __syncthreads();
        if (jt + 2 < njt) issue_kv(jt + 2);
    }

    // ---- epilogue: normalize, split-bf16 store to [B,S,D] ----
    float invA = 1.f / lA, invB = 1.f / lB;
    #pragma unroll
    for (int tn = 0; tn < 8; tn++) {
        int col = h*CDK + tn*8 + colL;
        #pragma unroll
        for (int rh = 0; rh < 2; rh++) {
            int q = q0 + w*16 + (lane >> 2) + rh*8;
            float inv = rh ? invB : invA;
            float v0 = o[tn][rh*2]   * inv;
            float v1 = o[tn][rh*2+1] * inv;
            __nv_bfloat16 h0, l0, h1, l1;
            split2(v0, h0, l0);
            split2(v1, h1, l1);
            size_t idx = (size_t)(b*CS + q) * CD + col;
            *(__nv_bfloat162*)(Oh + idx) = __halves2bfloat162(h0, h1);
            *(__nv_bfloat162*)(Ol + idx) = __halves2bfloat162(l0, l1);
        }
    }
}

// ---------------------------------------------------------------------------
extern "C" void kernel_launch(void* const* d_in, const int* in_sizes, int n_in,
                              void* d_out, int out_size)
{
    const float* x  = (const float*)d_in[0];
    // d_in[1] = mask (causal triu(k=1), handled analytically)
    const float* Wq = (const float*)d_in[2];
    const float* bq = (const float*)d_in[3];
    const float* Wk = (const float*)d_in[4];
    const float* bk = (const float*)d_in[5];
    const float* Wv = (const float*)d_in[6];
    const float* bv = (const float*)d_in[7];
    const float* Wo = (const float*)d_in[8];
    const float* bo = (const float*)d_in[9];
    float* out = (float*)d_out;

    __nv_bfloat16 *xh, *xl, *wh, *wl, *ah, *al, *qh, *ql, *kh, *kl, *vh, *vl;
    cudaGetSymbolAddress((void**)&xh, g_xh);
    cudaGetSymbolAddress((void**)&xl, g_xl);
    cudaGetSymbolAddress((void**)&wh, g_wh);
    cudaGetSymbolAddress((void**)&wl, g_wl);
    cudaGetSymbolAddress((void**)&ah, g_ah);
    cudaGetSymbolAddress((void**)&al, g_al);
    cudaGetSymbolAddress((void**)&qh, g_qh);
    cudaGetSymbolAddress((void**)&ql, g_ql);
    cudaGetSymbolAddress((void**)&kh, g_kh);
    cudaGetSymbolAddress((void**)&kl, g_kl);
    cudaGetSymbolAddress((void**)&vh, g_vh);
    cudaGetSymbolAddress((void**)&vl, g_vl);

    cudaFuncSetAttribute(attn_tc,  cudaFuncAttributeMaxDynamicSharedMemorySize, ATTN_SMEM);
    cudaFuncSetAttribute(gemm_qkv, cudaFuncAttributeMaxDynamicSharedMemorySize, GEMM_SMEM);
    cudaFuncSetAttribute(gemm_o,   cudaFuncAttributeMaxDynamicSharedMemorySize, GEMM_SMEM);

    trig_kernel<<<256, 256>>>();
    split_kernel<<<(CM*CD)/1024, 256>>>(x, xh, xl);
    wsplit_kernel<<<dim3(32,32), 256>>>(Wq, wh + 0*CD*CD, wl + 0*CD*CD);
    wsplit_kernel<<<dim3(32,32), 256>>>(Wk, wh + 1*CD*CD, wl + 1*CD*CD);
    wsplit_kernel<<<dim3(32,32), 256>>>(Wv, wh + 2*CD*CD, wl + 2*CD*CD);
    wsplit_kernel<<<dim3(32,32), 256>>>(Wo, wh + 3*CD*CD, wl + 3*CD*CD);

    gemm_qkv<<<dim3(CD/128, CM/128, 3), 256, GEMM_SMEM>>>(
        xh, xl, wh, wl, bq, bk, bv, qh, ql, kh, kl, vh, vl);

    attn_tc<<<dim3(CS/128, CH, CB), 256, ATTN_SMEM>>>(
        qh, ql, kh, kl, vh, vl, ah, al);

    gemm_o<<<dim3(CD/128, CM/128), 256, GEMM_SMEM>>>(
        ah, al, wh + 3*CD*CD, wl + 3*CD*CD, bo, out);
}

// round 5
// speedup vs baseline: 6.0197x; 2.2472x over previous
#include <cuda_runtime.h>
#include <cuda_fp16.h>
#include <math.h>
#include <stdint.h>

#define CB 2
#define CS 2048
#define CD 1024
#define CH 16
#define CDK 64
#define CM (CB*CS)   // 4096

// ---------------------------------------------------------------------------
// Scratch (__device__ globals; allocation-free rule)
// ---------------------------------------------------------------------------
__device__ float g_trig[CS*32*2];
__device__ __half g_x16[CM*CD];
__device__ __half g_w16[4][CD*CD];          // W^T fp16 (q,k,v,o)
__device__ __half g_q16[CB*CH*CS*CDK];
__device__ __half g_k16[CB*CH*CS*CDK];
__device__ __half g_v16[CB*CH*CS*CDK];
__device__ __half g_a16[CM*CD];             // attn out fp16

// ---------------------------------------------------------------------------
// Helpers
// ---------------------------------------------------------------------------
__device__ __forceinline__ uint32_t smem_u32(const void* p) {
    uint32_t a;
    asm("{ .reg .u64 t; cvta.to.shared.u64 t, %1; cvt.u32.u64 %0, t; }" : "=r"(a) : "l"(p));
    return a;
}

__device__ __forceinline__ void cpa16(uint32_t s, const void* g)
{
    asm volatile("cp.async.cg.shared.global [%0], [%1], 16;"
                 :: "r"(s), "l"(__cvta_generic_to_global(g)) : "memory");
}

__device__ __forceinline__ void ldsm4(uint32_t* r, uint32_t addr)
{
    asm volatile("ldmatrix.sync.aligned.m8n8.x4.shared.b16 {%0,%1,%2,%3}, [%4];"
                 : "=r"(r[0]), "=r"(r[1]), "=r"(r[2]), "=r"(r[3]) : "r"(addr));
}

__device__ __forceinline__ void ldsm4t(uint32_t* r, uint32_t addr)
{
    asm volatile("ldmatrix.sync.aligned.m8n8.x4.trans.shared.b16 {%0,%1,%2,%3}, [%4];"
                 : "=r"(r[0]), "=r"(r[1]), "=r"(r[2]), "=r"(r[3]) : "r"(addr));
}

__device__ __forceinline__ void mma_f16(float* c, const uint32_t* a, const uint32_t* b)
{
    asm volatile("mma.sync.aligned.m16n8k16.row.col.f32.f16.f16.f32 "
                 "{%0,%1,%2,%3}, {%4,%5,%6,%7}, {%8,%9}, {%0,%1,%2,%3};"
                 : "+f"(c[0]), "+f"(c[1]), "+f"(c[2]), "+f"(c[3])
                 : "r"(a[0]), "r"(a[1]), "r"(a[2]), "r"(a[3]), "r"(b[0]), "r"(b[1]));
}

__device__ __forceinline__ uint32_t packh2(float a, float b)
{
    __half2 t = __floats2half2_rn(a, b);
    return *(uint32_t*)&t;
}

// ---------------------------------------------------------------------------
// Prep kernels
// ---------------------------------------------------------------------------
__global__ void trig_kernel()
{
    int t = blockIdx.x * 256 + threadIdx.x;
    int s = t >> 5, i = t & 31;
    double theta = exp((double)i * (-log(10000.0) / 32.0));
    double a = (double)s * theta;
    g_trig[t*2]   = (float)cos(a);
    g_trig[t*2+1] = (float)sin(a);
}

__global__ void cvt_kernel(const float* __restrict__ src, __half* __restrict__ dst)
{
    int i = (blockIdx.x * 256 + threadIdx.x) * 4;
    float4 v = *(const float4*)(src + i);
    *(__half2*)(dst + i)     = __floats2half2_rn(v.x, v.y);
    *(__half2*)(dst + i + 2) = __floats2half2_rn(v.z, v.w);
}

// W[k][n] -> out[n][k] transposed fp16; z selects which of 4 weights
__global__ void wcvt_kernel(const float* __restrict__ W0, const float* __restrict__ W1,
                            const float* __restrict__ W2, const float* __restrict__ W3,
                            __half* __restrict__ out)
{
    __shared__ float t[32][33];
    const int z = blockIdx.z;
    const float* W = (z == 0) ? W0 : (z == 1) ? W1 : (z == 2) ? W2 : W3;
    __half* dst = out + (size_t)z * CD * CD;
    int bx = blockIdx.x * 32, by = blockIdx.y * 32;
    int tx = threadIdx.x & 31, ty = threadIdx.x >> 5;
    #pragma unroll
    for (int i = 0; i < 4; i++)
        t[ty + 8*i][tx] = W[(size_t)(by + ty + 8*i) * CD + bx + tx];
    __syncthreads();
    #pragma unroll
    for (int i = 0; i < 4; i++) {
        float x = t[tx][ty + 8*i];    // = W[by+tx][bx+ty+8i]
        dst[(size_t)(bx + ty + 8*i) * CD + by + tx] = __float2half_rn(x);
    }
}

// ---------------------------------------------------------------------------
// fp16 tensor-core GEMM via mma.sync: C[4096,1024] = A[M,K] @ B[N,K]^T + bias
// CTA 128x128, BK=64, 3-stage cp.async pipeline, 8 warps (4m x 2n).
// ---------------------------------------------------------------------------
#define ASTRIDE 144
#define MATB (128*144)          // 18432
#define BUFB (2*MATB)           // A, B
#define NSTAGE 3
#define GEMM_SMEM (NSTAGE*BUFB) // 110592

struct GArgs {
    const __half *A, *B;
    int m0, n0, tid;
    uint32_t s0;
};

__device__ __forceinline__ void issue_chunk(const GArgs& a, int chunk)
{
    int k0 = chunk << 6;
    uint32_t base = a.s0 + (chunk % NSTAGE) * BUFB;
    #pragma unroll
    for (int it = 0; it < 4; it++) {
        int c = a.tid + (it << 8);
        int row = c >> 3, seg = c & 7;
        uint32_t so = row * ASTRIDE + (seg << 4);
        cpa16(base        + so, a.A + (size_t)(a.m0 + row) * CD + k0 + (seg << 3));
        cpa16(base + MATB + so, a.B + (size_t)(a.n0 + row) * CD + k0 + (seg << 3));
    }
    asm volatile("cp.async.commit_group;" ::: "memory");
}

// Shared mainloop: accumulates 128x128 tile into acc.
__device__ __forceinline__ void gemm_mainloop(const GArgs& ga, float acc[2][8][4],
                                              int wm, int wn, int lane)
{
    issue_chunk(ga, 0);
    issue_chunk(ga, 1);

    const uint32_t a_off = (wm*32 + (lane & 15)) * ASTRIDE + ((lane >> 4) << 4);
    const uint32_t b_off = MATB +
        (wn*64 + (lane & 7) + ((lane >> 4) << 3)) * ASTRIDE + (((lane >> 3) & 1) << 4);

    for (int i = 0; i < 16; i++) {
        if (i < 15) asm volatile("cp.async.wait_group 1;" ::: "memory");
        else        asm volatile("cp.async.wait_group 0;" ::: "memory");
        __syncthreads();
        if (i + 2 < 16) issue_chunk(ga, i + 2);

        uint32_t buf = ga.s0 + (i % NSTAGE) * BUFB;
        #pragma unroll
        for (int ks = 0; ks < 4; ks++) {
            uint32_t af[2][4];
            #pragma unroll
            for (int tm = 0; tm < 2; tm++)
                ldsm4(af[tm], buf + a_off + tm*16*ASTRIDE + ks*32);
            #pragma unroll
            for (int tp = 0; tp < 4; tp++) {
                uint32_t bf4[4];
                ldsm4(bf4, buf + b_off + tp*16*ASTRIDE + ks*32);
                #pragma unroll
                for (int half = 0; half < 2; half++) {
                    int tn = tp*2 + half;
                    mma_f16(acc[0][tn], af[0], bf4 + half*2);
                    mma_f16(acc[1][tn], af[1], bf4 + half*2);
                }
            }
        }
        __syncthreads();
    }
}

// QKV fused; epilogue: bias, rope (q,k), q-prescale 1/8, fp16 scatter [B,H,S,DK]
__global__ __launch_bounds__(256)
void gemm_qkv(const __half* __restrict__ A, const __half* __restrict__ W16,
              const float* __restrict__ bq, const float* __restrict__ bk,
              const float* __restrict__ bv,
              __half* __restrict__ Q, __half* __restrict__ K, __half* __restrict__ V)
{
    extern __shared__ char smem[];
    const uint32_t s0 = smem_u32(smem);
    const int tid = threadIdx.x, wid = tid >> 5, lane = tid & 31;
    const int wm = wid & 3, wn = wid >> 2;
    const int m0 = blockIdx.y << 7, n0 = blockIdx.x << 7;
    const int z  = blockIdx.z;

    const __half* B = W16 + (size_t)z * CD * CD;
    const float* bias = (z == 0) ? bq : (z == 1) ? bk : bv;
    __half* D = (z == 0) ? Q : (z == 1) ? K : V;
    const bool rope = (z < 2);
    const float oscale = (z == 0) ? 0.125f : 1.0f;

    GArgs ga{A, B, m0, n0, tid, s0};

    float acc[2][8][4];
    #pragma unroll
    for (int i = 0; i < 2; i++)
        #pragma unroll
        for (int j = 0; j < 8; j++)
            #pragma unroll
            for (int r = 0; r < 4; r++) acc[i][j][r] = 0.f;

    gemm_mainloop(ga, acc, wm, wn, lane);

    #pragma unroll
    for (int tm = 0; tm < 2; tm++) {
        #pragma unroll
        for (int tn = 0; tn < 8; tn++) {
            int col = n0 + wn*64 + tn*8 + (lane & 3)*2;
            float b0 = bias[col], b1 = bias[col+1];
            acc[tm][tn][0] += b0; acc[tm][tn][1] += b1;
            acc[tm][tn][2] += b0; acc[tm][tn][3] += b1;
        }
    }

    if (rope) {
        #pragma unroll
        for (int tm = 0; tm < 2; tm++) {
            #pragma unroll
            for (int tn = 0; tn < 4; tn++) {
                #pragma unroll
                for (int r = 0; r < 4; r++) {
                    int row = m0 + wm*32 + tm*16 + (lane >> 2) + (r >> 1)*8;
                    int s   = row & (CS - 1);
                    int p   = tn*8 + (lane & 3)*2 + (r & 1);
                    float cc = g_trig[(s*32 + p)*2];
                    float sn = g_trig[(s*32 + p)*2 + 1];
                    float lo = acc[tm][tn][r], hi = acc[tm][tn+4][r];
                    acc[tm][tn][r]   = lo*cc - hi*sn;
                    acc[tm][tn+4][r] = hi*cc + lo*sn;
                }
            }
        }
    }

    #pragma unroll
    for (int tm = 0; tm < 2; tm++) {
        #pragma unroll
        for (int tn = 0; tn < 8; tn++) {
            int col = n0 + wn*64 + tn*8 + (lane & 3)*2;
            int h_ = col >> 6, dk = col & 63;
            #pragma unroll
            for (int rh = 0; rh < 2; rh++) {
                int row = m0 + wm*32 + tm*16 + (lane >> 2) + rh*8;
                int b_ = row >> 11, s_ = row & (CS - 1);
                size_t idx = ((size_t)((b_*CH + h_)*CS + s_)) * CDK + dk;
                *(__half2*)(D + idx) = __floats2half2_rn(acc[tm][tn][rh*2]   * oscale,
                                                         acc[tm][tn][rh*2+1] * oscale);
            }
        }
    }
}

// Output projection: row-major fp32 C.
__global__ __launch_bounds__(256)
void gemm_o(const __half* __restrict__ A, const __half* __restrict__ B,
            const float* __restrict__ bias, float* __restrict__ C)
{
    extern __shared__ char smem[];
    const uint32_t s0 = smem_u32(smem);
    const int tid = threadIdx.x, wid = tid >> 5, lane = tid & 31;
    const int wm = wid & 3, wn = wid >> 2;
    const int m0 = blockIdx.y << 7, n0 = blockIdx.x << 7;

    GArgs ga{A, B, m0, n0, tid, s0};

    float acc[2][8][4];
    #pragma unroll
    for (int i = 0; i < 2; i++)
        #pragma unroll
        for (int j = 0; j < 8; j++)
            #pragma unroll
            for (int r = 0; r < 4; r++) acc[i][j][r] = 0.f;

    gemm_mainloop(ga, acc, wm, wn, lane);

    #pragma unroll
    for (int tm = 0; tm < 2; tm++) {
        #pragma unroll
        for (int tn = 0; tn < 8; tn++) {
            int col = n0 + wn*64 + tn*8 + (lane & 3)*2;
            float b0 = bias[col], b1 = bias[col+1];
            #pragma unroll
            for (int rh = 0; rh < 2; rh++) {
                int row = m0 + wm*32 + tm*16 + (lane >> 2) + rh*8;
                float* dst = C + (size_t)row * CD + col;
                *(float2*)dst = make_float2(acc[tm][tn][rh*2] + b0,
                                            acc[tm][tn][rh*2+1] + b1);
            }
        }
    }
}

// ---------------------------------------------------------------------------
// fp16 tensor-core causal flash attention (mma.sync)
// CTA: (b, h, 128-row q-tile). 8 warps x 16 rows. KV tiles of 64, double-buffered.
// Q pre-scaled by 1/sqrt(DK) in the projection epilogue.
// ---------------------------------------------------------------------------
#define AT_STRIDE 144
#define AT_QMAT (128*AT_STRIDE)     // 18432
#define AT_KMAT (64*AT_STRIDE)      // 9216
#define AT_STAGE (2*AT_KMAT)        // 18432 (K, V)
#define ATTN_SMEM (AT_QMAT + 2*AT_STAGE)   // 55296

__global__ __launch_bounds__(256)
void attn_tc(const __half* __restrict__ Qg, const __half* __restrict__ Kg,
             const __half* __restrict__ Vg, __half* __restrict__ Og)
{
    extern __shared__ char smem[];
    const uint32_t s0 = smem_u32(smem);
    const int tid = threadIdx.x, w = tid >> 5, lane = tid & 31;

    const int qt = gridDim.x - 1 - blockIdx.x;        // heavy tiles first
    const int h  = blockIdx.y, b = blockIdx.z;
    const size_t g = (size_t)(b * CH + h) * CS * CDK;
    const int q0 = qt * 128;
    const int njt = 2*qt + 2;

    const __half *Q = Qg + g, *K = Kg + g, *V = Vg + g;

    const uint32_t sQ  = s0;
    const uint32_t sKV = s0 + AT_QMAT;

    auto issue_kv = [&](int jt) {
        int kv0 = jt * 64;
        uint32_t sb = sKV + (jt & 1) * AT_STAGE;
        #pragma unroll
        for (int it = 0; it < 2; it++) {
            int c = tid + (it << 8);      // 0..511
            int row = c >> 3, seg = c & 7;
            uint32_t so = row * AT_STRIDE + (seg << 4);
            size_t off = (size_t)(kv0 + row) * CDK + (seg << 3);
            cpa16(sb           + so, K + off);
            cpa16(sb + AT_KMAT + so, V + off);
        }
        asm volatile("cp.async.commit_group;" ::: "memory");
    };

    // Q load (grouped with kv tile 0)
    #pragma unroll
    for (int it = 0; it < 4; it++) {
        int c = tid + (it << 8);
        int row = c >> 3, seg = c & 7;
        cpa16(sQ + row * AT_STRIDE + (seg << 4), Q + (size_t)(q0 + row) * CDK + (seg << 3));
    }
    issue_kv(0);
    if (njt > 1) issue_kv(1);

    const uint32_t q_off = (w*16 + (lane & 15)) * AT_STRIDE + ((lane >> 4) << 4);
    const uint32_t k_pat = ((lane & 7) + ((lane >> 4) << 3)) * AT_STRIDE + (((lane >> 3) & 1) << 4);
    const uint32_t v_pat = ((lane & 7) + (((lane >> 3) & 1) << 3)) * AT_STRIDE + ((lane >> 4) << 4);

    uint32_t qf[4][4];
    float o[8][4];
    #pragma unroll
    for (int j = 0; j < 8; j++)
        #pragma unroll
        for (int r = 0; r < 4; r++) o[j][r] = 0.f;
    float mA = -1e30f, mB = -1e30f, lA = 0.f, lB = 0.f;

    const int rowA_g = q0 + w*16 + (lane >> 2);
    const int colL   = (lane & 3) * 2;

    for (int jt = 0; jt < njt; jt++) {
        if (jt + 1 < njt) asm volatile("cp.async.wait_group 1;" ::: "memory");
        else              asm volatile("cp.async.wait_group 0;" ::: "memory");
        __syncthreads();

        if (jt == 0) {
            #pragma unroll
            for (int kc = 0; kc < 4; kc++)
                ldsm4(qf[kc], sQ + q_off + kc*32);
        }

        const uint32_t sb = sKV + (jt & 1) * AT_STAGE;
        const int kv0 = jt * 64;

        // ---- S = Q K^T ----
        float s[8][4];
        #pragma unroll
        for (int j = 0; j < 8; j++)
            #pragma unroll
            for (int r = 0; r < 4; r++) s[j][r] = 0.f;

        #pragma unroll
        for (int kc = 0; kc < 4; kc++) {
            #pragma unroll
            for (int np = 0; np < 4; np++) {
                uint32_t kf4[4];
                ldsm4(kf4, sb + k_pat + np*16*AT_STRIDE + kc*32);
                mma_f16(s[np*2],   qf[kc], kf4);
                mma_f16(s[np*2+1], qf[kc], kf4 + 2);
            }
        }

        // ---- mask + online softmax ----
        if (jt >= 2*qt) {
            #pragma unroll
            for (int tn = 0; tn < 8; tn++) {
                int col = kv0 + tn*8 + colL;
                if (col     > rowA_g) s[tn][0] = -1e30f;
                if (col + 1 > rowA_g) s[tn][1] = -1e30f;
                if (col     > rowA_g + 8) s[tn][2] = -1e30f;
                if (col + 1 > rowA_g + 8) s[tn][3] = -1e30f;
            }
        }

        float mxA = -1e30f, mxB = -1e30f;
        #pragma unroll
        for (int tn = 0; tn < 8; tn++) {
            mxA = fmaxf(mxA, fmaxf(s[tn][0], s[tn][1]));
            mxB = fmaxf(mxB, fmaxf(s[tn][2], s[tn][3]));
        }
        mxA = fmaxf(mxA, __shfl_xor_sync(0xffffffffu, mxA, 1));
        mxA = fmaxf(mxA, __shfl_xor_sync(0xffffffffu, mxA, 2));
        mxB = fmaxf(mxB, __shfl_xor_sync(0xffffffffu, mxB, 1));
        mxB = fmaxf(mxB, __shfl_xor_sync(0xffffffffu, mxB, 2));

        float nmA = fmaxf(mA, mxA), nmB = fmaxf(mB, mxB);
        float facA = __expf(mA - nmA), facB = __expf(mB - nmB);

        float sumA = 0.f, sumB = 0.f;
        #pragma unroll
        for (int tn = 0; tn < 8; tn++) {
            s[tn][0] = __expf(s[tn][0] - nmA);
            s[tn][1] = __expf(s[tn][1] - nmA);
            s[tn][2] = __expf(s[tn][2] - nmB);
            s[tn][3] = __expf(s[tn][3] - nmB);
            sumA += s[tn][0] + s[tn][1];
            sumB += s[tn][2] + s[tn][3];
        }
        sumA += __shfl_xor_sync(0xffffffffu, sumA, 1);
        sumA += __shfl_xor_sync(0xffffffffu, sumA, 2);
        sumB += __shfl_xor_sync(0xffffffffu, sumB, 1);
        sumB += __shfl_xor_sync(0xffffffffu, sumB, 2);

        lA = lA*facA + sumA;  mA = nmA;
        lB = lB*facB + sumB;  mB = nmB;

        #pragma unroll
        for (int tn = 0; tn < 8; tn++) {
            o[tn][0] *= facA; o[tn][1] *= facA;
            o[tn][2] *= facB; o[tn][3] *= facB;
        }

        // ---- O += P V ----
        #pragma unroll
        for (int kc = 0; kc < 4; kc++) {
            uint32_t pa[4];
            pa[0] = packh2(s[2*kc][0],   s[2*kc][1]);
            pa[1] = packh2(s[2*kc][2],   s[2*kc][3]);
            pa[2] = packh2(s[2*kc+1][0], s[2*kc+1][1]);
            pa[3] = packh2(s[2*kc+1][2], s[2*kc+1][3]);
            #pragma unroll
            for (int np = 0; np < 4; np++) {
                uint32_t vf4[4];
                ldsm4t(vf4, sb + AT_KMAT + v_pat + kc*16*AT_STRIDE + np*32);
                mma_f16(o[np*2],   pa, vf4);
                mma_f16(o[np*2+1], pa, vf4 + 2);
            }
        }

        __syncthreads();
        if (jt + 2 < njt) issue_kv(jt + 2);
    }

    // ---- epilogue: normalize, fp16 store to [B,S,D] ----
    float invA = 1.f / lA, invB = 1.f / lB;
    #pragma unroll
    for (int tn = 0; tn < 8; tn++) {
        int col = h*CDK + tn*8 + colL;
        #pragma unroll
        for (int rh = 0; rh < 2; rh++) {
            int q = q0 + w*16 + (lane >> 2) + rh*8;
            float inv = rh ? invB : invA;
            size_t idx = (size_t)(b*CS + q) * CD + col;
            *(__half2*)(Og + idx) = __floats2half2_rn(o[tn][rh*2] * inv,
                                                      o[tn][rh*2+1] * inv);
        }
    }
}

// ---------------------------------------------------------------------------
extern "C" void kernel_launch(void* const* d_in, const int* in_sizes, int n_in,
                              void* d_out, int out_size)
{
    const float* x  = (const float*)d_in[0];
    // d_in[1] = mask (causal triu(k=1), handled analytically)
    const float* Wq = (const float*)d_in[2];
    const float* bq = (const float*)d_in[3];
    const float* Wk = (const float*)d_in[4];
    const float* bk = (const float*)d_in[5];
    const float* Wv = (const float*)d_in[6];
    const float* bv = (const float*)d_in[7];
    const float* Wo = (const float*)d_in[8];
    const float* bo = (const float*)d_in[9];
    float* out = (float*)d_out;

    __half *x16, *w16, *q16, *k16, *v16, *a16;
    cudaGetSymbolAddress((void**)&x16, g_x16);
    cudaGetSymbolAddress((void**)&w16, g_w16);
    cudaGetSymbolAddress((void**)&q16, g_q16);
    cudaGetSymbolAddress((void**)&k16, g_k16);
    cudaGetSymbolAddress((void**)&v16, g_v16);
    cudaGetSymbolAddress((void**)&a16, g_a16);

    cudaFuncSetAttribute(attn_tc,  cudaFuncAttributeMaxDynamicSharedMemorySize, ATTN_SMEM);
    cudaFuncSetAttribute(gemm_qkv, cudaFuncAttributeMaxDynamicSharedMemorySize, GEMM_SMEM);
    cudaFuncSetAttribute(gemm_o,   cudaFuncAttributeMaxDynamicSharedMemorySize, GEMM_SMEM);

    trig_kernel<<<256, 256>>>();
    cvt_kernel<<<(CM*CD)/1024, 256>>>(x, x16);
    wcvt_kernel<<<dim3(32,32,4), 256>>>(Wq, Wk, Wv, Wo, w16);

    gemm_qkv<<<dim3(CD/128, CM/128, 3), 256, GEMM_SMEM>>>(
        x16, w16, bq, bk, bv, q16, k16, v16);

    attn_tc<<<dim3(CS/128, CH, CB), 256, ATTN_SMEM>>>(q16, k16, v16, a16);

    gemm_o<<<dim3(CD/128, CM/128), 256, GEMM_SMEM>>>(
        a16, w16 + 3*(size_t)CD*CD, bo, out);
}

// round 6
// speedup vs baseline: 6.1288x; 1.0181x over previous
#include <cuda_runtime.h>
#include <cuda_fp16.h>
#include <math.h>
#include <stdint.h>

#define CB 2
#define CS 2048
#define CD 1024
#define CH 16
#define CDK 64
#define CM (CB*CS)   // 4096

// ---------------------------------------------------------------------------
// Scratch (__device__ globals; allocation-free rule)
// ---------------------------------------------------------------------------
__device__ float g_trig[CS*32*2];
__device__ __half g_x16[CM*CD];
__device__ __half g_w16[4][CD*CD];          // W^T fp16 (q,k,v,o)
__device__ __half g_q16[CB*CH*CS*CDK];
__device__ __half g_k16[CB*CH*CS*CDK];
__device__ __half g_v16[CB*CH*CS*CDK];
__device__ __half g_a16[CM*CD];             // attn out fp16

// ---------------------------------------------------------------------------
// Helpers
// ---------------------------------------------------------------------------
__device__ __forceinline__ uint32_t smem_u32(const void* p) {
    uint32_t a;
    asm("{ .reg .u64 t; cvta.to.shared.u64 t, %1; cvt.u32.u64 %0, t; }" : "=r"(a) : "l"(p));
    return a;
}

__device__ __forceinline__ void cpa16(uint32_t s, const void* g)
{
    asm volatile("cp.async.cg.shared.global [%0], [%1], 16;"
                 :: "r"(s), "l"(__cvta_generic_to_global(g)) : "memory");
}

__device__ __forceinline__ void ldsm4(uint32_t* r, uint32_t addr)
{
    asm volatile("ldmatrix.sync.aligned.m8n8.x4.shared.b16 {%0,%1,%2,%3}, [%4];"
                 : "=r"(r[0]), "=r"(r[1]), "=r"(r[2]), "=r"(r[3]) : "r"(addr));
}

__device__ __forceinline__ void ldsm4t(uint32_t* r, uint32_t addr)
{
    asm volatile("ldmatrix.sync.aligned.m8n8.x4.trans.shared.b16 {%0,%1,%2,%3}, [%4];"
                 : "=r"(r[0]), "=r"(r[1]), "=r"(r[2]), "=r"(r[3]) : "r"(addr));
}

__device__ __forceinline__ void mma_f16(float* c, const uint32_t* a, const uint32_t* b)
{
    asm volatile("mma.sync.aligned.m16n8k16.row.col.f32.f16.f16.f32 "
                 "{%0,%1,%2,%3}, {%4,%5,%6,%7}, {%8,%9}, {%0,%1,%2,%3};"
                 : "+f"(c[0]), "+f"(c[1]), "+f"(c[2]), "+f"(c[3])
                 : "r"(a[0]), "r"(a[1]), "r"(a[2]), "r"(a[3]), "r"(b[0]), "r"(b[1]));
}

__device__ __forceinline__ uint32_t packh2(float a, float b)
{
    __half2 t = __floats2half2_rn(a, b);
    return *(uint32_t*)&t;
}

// ---------------------------------------------------------------------------
// Prep kernels
// ---------------------------------------------------------------------------
__global__ void trig_kernel()
{
    int t = blockIdx.x * 256 + threadIdx.x;
    int s = t >> 5, i = t & 31;
    double theta = exp((double)i * (-log(10000.0) / 32.0));
    double a = (double)s * theta;
    g_trig[t*2]   = (float)cos(a);
    g_trig[t*2+1] = (float)sin(a);
}

__global__ void cvt_kernel(const float* __restrict__ src, __half* __restrict__ dst)
{
    int i = (blockIdx.x * 256 + threadIdx.x) * 4;
    float4 v = *(const float4*)(src + i);
    *(__half2*)(dst + i)     = __floats2half2_rn(v.x, v.y);
    *(__half2*)(dst + i + 2) = __floats2half2_rn(v.z, v.w);
}

// W[k][n] -> out[n][k] transposed fp16; z selects which of 4 weights
__global__ void wcvt_kernel(const float* __restrict__ W0, const float* __restrict__ W1,
                            const float* __restrict__ W2, const float* __restrict__ W3,
                            __half* __restrict__ out)
{
    __shared__ float t[32][33];
    const int z = blockIdx.z;
    const float* W = (z == 0) ? W0 : (z == 1) ? W1 : (z == 2) ? W2 : W3;
    __half* dst = out + (size_t)z * CD * CD;
    int bx = blockIdx.x * 32, by = blockIdx.y * 32;
    int tx = threadIdx.x & 31, ty = threadIdx.x >> 5;
    #pragma unroll
    for (int i = 0; i < 4; i++)
        t[ty + 8*i][tx] = W[(size_t)(by + ty + 8*i) * CD + bx + tx];
    __syncthreads();
    #pragma unroll
    for (int i = 0; i < 4; i++) {
        float x = t[tx][ty + 8*i];    // = W[by+tx][bx+ty+8i]
        dst[(size_t)(bx + ty + 8*i) * CD + by + tx] = __float2half_rn(x);
    }
}

// ---------------------------------------------------------------------------
// fp16 tensor-core GEMM via mma.sync: C[4096,1024] = A[M,K] @ B[N,K]^T + bias
// CTA 128x128, BK=64, 2-stage cp.async double buffer, 8 warps (4m x 2n).
// 2 CTAs/SM (smem 73.7KB, regs capped at 128).
// ---------------------------------------------------------------------------
#define ASTRIDE 144
#define MATB (128*144)          // 18432
#define BUFB (2*MATB)           // A, B
#define NSTAGE 2
#define GEMM_SMEM (NSTAGE*BUFB) // 73728

struct GArgs {
    const __half *A, *B;
    int m0, n0, tid;
    uint32_t s0;
};

__device__ __forceinline__ void issue_chunk(const GArgs& a, int chunk)
{
    int k0 = chunk << 6;
    uint32_t base = a.s0 + (chunk & 1) * BUFB;
    #pragma unroll
    for (int it = 0; it < 4; it++) {
        int c = a.tid + (it << 8);
        int row = c >> 3, seg = c & 7;
        uint32_t so = row * ASTRIDE + (seg << 4);
        cpa16(base        + so, a.A + (size_t)(a.m0 + row) * CD + k0 + (seg << 3));
        cpa16(base + MATB + so, a.B + (size_t)(a.n0 + row) * CD + k0 + (seg << 3));
    }
    asm volatile("cp.async.commit_group;" ::: "memory");
}

// Shared mainloop: accumulates 128x128 tile into acc. Double-buffered:
// issue chunk i+1 at top (buffer safe: trailing sync of iter i-1), then wait i.
__device__ __forceinline__ void gemm_mainloop(const GArgs& ga, float acc[2][8][4],
                                              int wm, int wn, int lane)
{
    issue_chunk(ga, 0);

    const uint32_t a_off = (wm*32 + (lane & 15)) * ASTRIDE + ((lane >> 4) << 4);
    const uint32_t b_off = MATB +
        (wn*64 + (lane & 7) + ((lane >> 4) << 3)) * ASTRIDE + (((lane >> 3) & 1) << 4);

    for (int i = 0; i < 16; i++) {
        if (i + 1 < 16) {
            issue_chunk(ga, i + 1);
            asm volatile("cp.async.wait_group 1;" ::: "memory");
        } else {
            asm volatile("cp.async.wait_group 0;" ::: "memory");
        }
        __syncthreads();

        uint32_t buf = ga.s0 + (i & 1) * BUFB;
        #pragma unroll
        for (int ks = 0; ks < 4; ks++) {
            uint32_t af[2][4];
            #pragma unroll
            for (int tm = 0; tm < 2; tm++)
                ldsm4(af[tm], buf + a_off + tm*16*ASTRIDE + ks*32);
            #pragma unroll
            for (int tp = 0; tp < 4; tp++) {
                uint32_t bf4[4];
                ldsm4(bf4, buf + b_off + tp*16*ASTRIDE + ks*32);
                #pragma unroll
                for (int half = 0; half < 2; half++) {
                    int tn = tp*2 + half;
                    mma_f16(acc[0][tn], af[0], bf4 + half*2);
                    mma_f16(acc[1][tn], af[1], bf4 + half*2);
                }
            }
        }
        __syncthreads();   // buffer (i&1) free for issue of i+2 next iteration
    }
}

// QKV fused; epilogue: bias, rope (q,k), q-prescale 1/8, fp16 scatter [B,H,S,DK]
__global__ __launch_bounds__(256, 2)
void gemm_qkv(const __half* __restrict__ A, const __half* __restrict__ W16,
              const float* __restrict__ bq, const float* __restrict__ bk,
              const float* __restrict__ bv,
              __half* __restrict__ Q, __half* __restrict__ K, __half* __restrict__ V)
{
    extern __shared__ char smem[];
    const uint32_t s0 = smem_u32(smem);
    const int tid = threadIdx.x, wid = tid >> 5, lane = tid & 31;
    const int wm = wid & 3, wn = wid >> 2;
    const int m0 = blockIdx.y << 7, n0 = blockIdx.x << 7;
    const int z  = blockIdx.z;

    const __half* B = W16 + (size_t)z * CD * CD;
    const float* bias = (z == 0) ? bq : (z == 1) ? bk : bv;
    __half* D = (z == 0) ? Q : (z == 1) ? K : V;
    const bool rope = (z < 2);
    const float oscale = (z == 0) ? 0.125f : 1.0f;

    GArgs ga{A, B, m0, n0, tid, s0};

    float acc[2][8][4];
    #pragma unroll
    for (int i = 0; i < 2; i++)
        #pragma unroll
        for (int j = 0; j < 8; j++)
            #pragma unroll
            for (int r = 0; r < 4; r++) acc[i][j][r] = 0.f;

    gemm_mainloop(ga, acc, wm, wn, lane);

    #pragma unroll
    for (int tm = 0; tm < 2; tm++) {
        #pragma unroll
        for (int tn = 0; tn < 8; tn++) {
            int col = n0 + wn*64 + tn*8 + (lane & 3)*2;
            float b0 = bias[col], b1 = bias[col+1];
            acc[tm][tn][0] += b0; acc[tm][tn][1] += b1;
            acc[tm][tn][2] += b0; acc[tm][tn][3] += b1;
        }
    }

    if (rope) {
        #pragma unroll
        for (int tm = 0; tm < 2; tm++) {
            #pragma unroll
            for (int tn = 0; tn < 4; tn++) {
                #pragma unroll
                for (int r = 0; r < 4; r++) {
                    int row = m0 + wm*32 + tm*16 + (lane >> 2) + (r >> 1)*8;
                    int s   = row & (CS - 1);
                    int p   = tn*8 + (lane & 3)*2 + (r & 1);
                    float cc = g_trig[(s*32 + p)*2];
                    float sn = g_trig[(s*32 + p)*2 + 1];
                    float lo = acc[tm][tn][r], hi = acc[tm][tn+4][r];
                    acc[tm][tn][r]   = lo*cc - hi*sn;
                    acc[tm][tn+4][r] = hi*cc + lo*sn;
                }
            }
        }
    }

    #pragma unroll
    for (int tm = 0; tm < 2; tm++) {
        #pragma unroll
        for (int tn = 0; tn < 8; tn++) {
            int col = n0 + wn*64 + tn*8 + (lane & 3)*2;
            int h_ = col >> 6, dk = col & 63;
            #pragma unroll
            for (int rh = 0; rh < 2; rh++) {
                int row = m0 + wm*32 + tm*16 + (lane >> 2) + rh*8;
                int b_ = row >> 11, s_ = row & (CS - 1);
                size_t idx = ((size_t)((b_*CH + h_)*CS + s_)) * CDK + dk;
                *(__half2*)(D + idx) = __floats2half2_rn(acc[tm][tn][rh*2]   * oscale,
                                                         acc[tm][tn][rh*2+1] * oscale);
            }
        }
    }
}

// Output projection: row-major fp32 C.
__global__ __launch_bounds__(256, 2)
void gemm_o(const __half* __restrict__ A, const __half* __restrict__ B,
            const float* __restrict__ bias, float* __restrict__ C)
{
    extern __shared__ char smem[];
    const uint32_t s0 = smem_u32(smem);
    const int tid = threadIdx.x, wid = tid >> 5, lane = tid & 31;
    const int wm = wid & 3, wn = wid >> 2;
    const int m0 = blockIdx.y << 7, n0 = blockIdx.x << 7;

    GArgs ga{A, B, m0, n0, tid, s0};

    float acc[2][8][4];
    #pragma unroll
    for (int i = 0; i < 2; i++)
        #pragma unroll
        for (int j = 0; j < 8; j++)
            #pragma unroll
            for (int r = 0; r < 4; r++) acc[i][j][r] = 0.f;

    gemm_mainloop(ga, acc, wm, wn, lane);

    #pragma unroll
    for (int tm = 0; tm < 2; tm++) {
        #pragma unroll
        for (int tn = 0; tn < 8; tn++) {
            int col = n0 + wn*64 + tn*8 + (lane & 3)*2;
            float b0 = bias[col], b1 = bias[col+1];
            #pragma unroll
            for (int rh = 0; rh < 2; rh++) {
                int row = m0 + wm*32 + tm*16 + (lane >> 2) + rh*8;
                float* dst = C + (size_t)row * CD + col;
                *(float2*)dst = make_float2(acc[tm][tn][rh*2] + b0,
                                            acc[tm][tn][rh*2+1] + b1);
            }
        }
    }
}

// ---------------------------------------------------------------------------
// fp16 tensor-core causal flash attention (mma.sync)
// CTA: (b, h, 128-row q-tile). 8 warps x 16 rows. KV tiles of 64, double-buffered.
// Q pre-scaled by 1/sqrt(DK). 2 CTAs/SM (smem 55KB, regs capped 128).
// ---------------------------------------------------------------------------
#define AT_STRIDE 144
#define AT_QMAT (128*AT_STRIDE)     // 18432
#define AT_KMAT (64*AT_STRIDE)      // 9216
#define AT_STAGE (2*AT_KMAT)        // 18432 (K, V)
#define ATTN_SMEM (AT_QMAT + 2*AT_STAGE)   // 55296

__global__ __launch_bounds__(256, 2)
void attn_tc(const __half* __restrict__ Qg, const __half* __restrict__ Kg,
             const __half* __restrict__ Vg, __half* __restrict__ Og)
{
    extern __shared__ char smem[];
    const uint32_t s0 = smem_u32(smem);
    const int tid = threadIdx.x, w = tid >> 5, lane = tid & 31;

    const int qt = gridDim.x - 1 - blockIdx.x;        // heavy tiles first
    const int h  = blockIdx.y, b = blockIdx.z;
    const size_t g = (size_t)(b * CH + h) * CS * CDK;
    const int q0 = qt * 128;
    const int njt = 2*qt + 2;

    const __half *Q = Qg + g, *K = Kg + g, *V = Vg + g;

    const uint32_t sQ  = s0;
    const uint32_t sKV = s0 + AT_QMAT;

    auto issue_kv = [&](int jt) {
        int kv0 = jt * 64;
        uint32_t sb = sKV + (jt & 1) * AT_STAGE;
        #pragma unroll
        for (int it = 0; it < 2; it++) {
            int c = tid + (it << 8);      // 0..511
            int row = c >> 3, seg = c & 7;
            uint32_t so = row * AT_STRIDE + (seg << 4);
            size_t off = (size_t)(kv0 + row) * CDK + (seg << 3);
            cpa16(sb           + so, K + off);
            cpa16(sb + AT_KMAT + so, V + off);
        }
        asm volatile("cp.async.commit_group;" ::: "memory");
    };

    // Q load (grouped with kv tile 0)
    #pragma unroll
    for (int it = 0; it < 4; it++) {
        int c = tid + (it << 8);
        int row = c >> 3, seg = c & 7;
        cpa16(sQ + row * AT_STRIDE + (seg << 4), Q + (size_t)(q0 + row) * CDK + (seg << 3));
    }
    issue_kv(0);
    if (njt > 1) issue_kv(1);

    const uint32_t q_off = (w*16 + (lane & 15)) * AT_STRIDE + ((lane >> 4) << 4);
    const uint32_t k_pat = ((lane & 7) + ((lane >> 4) << 3)) * AT_STRIDE + (((lane >> 3) & 1) << 4);
    const uint32_t v_pat = ((lane & 7) + (((lane >> 3) & 1) << 3)) * AT_STRIDE + ((lane >> 4) << 4);

    uint32_t qf[4][4];
    float o[8][4];
    #pragma unroll
    for (int j = 0; j < 8; j++)
        #pragma unroll
        for (int r = 0; r < 4; r++) o[j][r] = 0.f;
    float mA = -1e30f, mB = -1e30f, lA = 0.f, lB = 0.f;

    const int rowA_g = q0 + w*16 + (lane >> 2);
    const int colL   = (lane & 3) * 2;

    for (int jt = 0; jt < njt; jt++) {
        if (jt + 1 < njt) asm volatile("cp.async.wait_group 1;" ::: "memory");
        else              asm volatile("cp.async.wait_group 0;" ::: "memory");
        __syncthreads();

        if (jt == 0) {
            #pragma unroll
            for (int kc = 0; kc < 4; kc++)
                ldsm4(qf[kc], sQ + q_off + kc*32);
        }

        const uint32_t sb = sKV + (jt & 1) * AT_STAGE;
        const int kv0 = jt * 64;

        // ---- S = Q K^T ----
        float s[8][4];
        #pragma unroll
        for (int j = 0; j < 8; j++)
            #pragma unroll
            for (int r = 0; r < 4; r++) s[j][r] = 0.f;

        #pragma unroll
        for (int kc = 0; kc < 4; kc++) {
            #pragma unroll
            for (int np = 0; np < 4; np++) {
                uint32_t kf4[4];
                ldsm4(kf4, sb + k_pat + np*16*AT_STRIDE + kc*32);
                mma_f16(s[np*2],   qf[kc], kf4);
                mma_f16(s[np*2+1], qf[kc], kf4 + 2);
            }
        }

        // ---- mask + online softmax ----
        if (jt >= 2*qt) {
            #pragma unroll
            for (int tn = 0; tn < 8; tn++) {
                int col = kv0 + tn*8 + colL;
                if (col     > rowA_g) s[tn][0] = -1e30f;
                if (col + 1 > rowA_g) s[tn][1] = -1e30f;
                if (col     > rowA_g + 8) s[tn][2] = -1e30f;
                if (col + 1 > rowA_g + 8) s[tn][3] = -1e30f;
            }
        }

        float mxA = -1e30f, mxB = -1e30f;
        #pragma unroll
        for (int tn = 0; tn < 8; tn++) {
            mxA = fmaxf(mxA, fmaxf(s[tn][0], s[tn][1]));
            mxB = fmaxf(mxB, fmaxf(s[tn][2], s[tn][3]));
        }
        mxA = fmaxf(mxA, __shfl_xor_sync(0xffffffffu, mxA, 1));
        mxA = fmaxf(mxA, __shfl_xor_sync(0xffffffffu, mxA, 2));
        mxB = fmaxf(mxB, __shfl_xor_sync(0xffffffffu, mxB, 1));
        mxB = fmaxf(mxB, __shfl_xor_sync(0xffffffffu, mxB, 2));

        float nmA = fmaxf(mA, mxA), nmB = fmaxf(mB, mxB);
        float facA = __expf(mA - nmA), facB = __expf(mB - nmB);

        float sumA = 0.f, sumB = 0.f;
        #pragma unroll
        for (int tn = 0; tn < 8; tn++) {
            s[tn][0] = __expf(s[tn][0] - nmA);
            s[tn][1] = __expf(s[tn][1] - nmA);
            s[tn][2] = __expf(s[tn][2] - nmB);
            s[tn][3] = __expf(s[tn][3] - nmB);
            sumA += s[tn][0] + s[tn][1];
            sumB += s[tn][2] + s[tn][3];
        }
        sumA += __shfl_xor_sync(0xffffffffu, sumA, 1);
        sumA += __shfl_xor_sync(0xffffffffu, sumA, 2);
        sumB += __shfl_xor_sync(0xffffffffu, sumB, 1);
        sumB += __shfl_xor_sync(0xffffffffu, sumB, 2);

        lA = lA*facA + sumA;  mA = nmA;
        lB = lB*facB + sumB;  mB = nmB;

        #pragma unroll
        for (int tn = 0; tn < 8; tn++) {
            o[tn][0] *= facA; o[tn][1] *= facA;
            o[tn][2] *= facB; o[tn][3] *= facB;
        }

        // ---- O += P V ----
        #pragma unroll
        for (int kc = 0; kc < 4; kc++) {
            uint32_t pa[4];
            pa[0] = packh2(s[2*kc][0],   s[2*kc][1]);
            pa[1] = packh2(s[2*kc][2],   s[2*kc][3]);
            pa[2] = packh2(s[2*kc+1][0], s[2*kc+1][1]);
            pa[3] = packh2(s[2*kc+1][2], s[2*kc+1][3]);
            #pragma unroll
            for (int np = 0; np < 4; np++) {
                uint32_t vf4[4];
                ldsm4t(vf4, sb + AT_KMAT + v_pat + kc*16*AT_STRIDE + np*32);
                mma_f16(o[np*2],   pa, vf4);
                mma_f16(o[np*2+1], pa, vf4 + 2);
            }
        }

        __syncthreads();
        if (jt + 2 < njt) issue_kv(jt + 2);
    }

    // ---- epilogue: normalize, fp16 store to [B,S,D] ----
    float invA = 1.f / lA, invB = 1.f / lB;
    #pragma unroll
    for (int tn = 0; tn < 8; tn++) {
        int col = h*CDK + tn*8 + colL;
        #pragma unroll
        for (int rh = 0; rh < 2; rh++) {
            int q = q0 + w*16 + (lane >> 2) + rh*8;
            float inv = rh ? invB : invA;
            size_t idx = (size_t)(b*CS + q) * CD + col;
            *(__half2*)(Og + idx) = __floats2half2_rn(o[tn][rh*2] * inv,
                                                      o[tn][rh*2+1] * inv);
        }
    }
}

// ---------------------------------------------------------------------------
extern "C" void kernel_launch(void* const* d_in, const int* in_sizes, int n_in,
                              void* d_out, int out_size)
{
    const float* x  = (const float*)d_in[0];
    // d_in[1] = mask (causal triu(k=1), handled analytically)
    const float* Wq = (const float*)d_in[2];
    const float* bq = (const float*)d_in[3];
    const float* Wk = (const float*)d_in[4];
    const float* bk = (const float*)d_in[5];
    const float* Wv = (const float*)d_in[6];
    const float* bv = (const float*)d_in[7];
    const float* Wo = (const float*)d_in[8];
    const float* bo = (const float*)d_in[9];
    float* out = (float*)d_out;

    __half *x16, *w16, *q16, *k16, *v16, *a16;
    cudaGetSymbolAddress((void**)&x16, g_x16);
    cudaGetSymbolAddress((void**)&w16, g_w16);
    cudaGetSymbolAddress((void**)&q16, g_q16);
    cudaGetSymbolAddress((void**)&k16, g_k16);
    cudaGetSymbolAddress((void**)&v16, g_v16);
    cudaGetSymbolAddress((void**)&a16, g_a16);

    cudaFuncSetAttribute(attn_tc,  cudaFuncAttributeMaxDynamicSharedMemorySize, ATTN_SMEM);
    cudaFuncSetAttribute(gemm_qkv, cudaFuncAttributeMaxDynamicSharedMemorySize, GEMM_SMEM);
    cudaFuncSetAttribute(gemm_o,   cudaFuncAttributeMaxDynamicSharedMemorySize, GEMM_SMEM);

    trig_kernel<<<256, 256>>>();
    cvt_kernel<<<(CM*CD)/1024, 256>>>(x, x16);
    wcvt_kernel<<<dim3(32,32,4), 256>>>(Wq, Wk, Wv, Wo, w16);

    gemm_qkv<<<dim3(CD/128, CM/128, 3), 256, GEMM_SMEM>>>(
        x16, w16, bq, bk, bv, q16, k16, v16);

    attn_tc<<<dim3(CS/128, CH, CB), 256, ATTN_SMEM>>>(q16, k16, v16, a16);

    gemm_o<<<dim3(CD/128, CM/128), 256, GEMM_SMEM>>>(
        a16, w16 + 3*(size_t)CD*CD, bo, out);
}